// round 2
// baseline (speedup 1.0000x reference)
#include <cuda_runtime.h>
#include <math.h>

#define Bc 256
#define Nc 1024
#define Ec 256
#define Hc 8
#define Tc 64
#define SEG 4
#define NSEG 256        // N / SEG
#define SUBN 32         // n rows staged in smem per chunk
#define NEG_BIG (-1e30f)
#define CLIPC 10.0f

// ---------------- persistent device state (no allocs allowed) ----------------
__device__ float g_sumx[Bc][Ec];          // running sum of unvisited x
__device__ float g_cnt[Bc];               // unvisited count
__device__ float g_cap[Bc];               // remaining capacity
__device__ int   g_cur[Bc];               // current node
__device__ unsigned char g_visited[Bc][Nc];
__device__ unsigned char g_mask[Bc][Nc];
__device__ float g_qk[Bc][Hc][Ec];        // folded query-key vectors (incl. scale)
__device__ float g_sbias[Bc][Hc];         // scale * q . bk
__device__ float g_part[Bc][SEG][Hc][Ec + 2];  // flash partials: m, l, acc[256]
__device__ float g_qpk[Bc][Ec];           // pointer query folded through Wpk
__device__ float g_ub[Bc];                // qp . bpk
__device__ float g_u[Bc][Nc];             // masked pointer logits

// ---------------- init: per-launch state reset + column sums of x ------------
__global__ void k_init(const float* __restrict__ x, const float* __restrict__ cap0) {
    int b = blockIdx.x, t = threadIdx.x;  // 256 threads
    const float* xb = x + (size_t)b * Nc * Ec;
    float s = 0.f;
    for (int n = 0; n < Nc; n++) s += xb[(size_t)n * Ec + t];
    g_sumx[b][t] = s;
    for (int i = t; i < Nc; i += 256) g_visited[b][i] = 0;
    if (t == 0) {
        g_cnt[b] = (float)Nc;
        g_cap[b] = cap0[b];
        g_cur[b] = 0;
    }
}

// ---------------- K1: mask + vehicle embed + q + folded qk -------------------
__global__ void k_state(const float* __restrict__ x, const float* __restrict__ demand,
                        const float* __restrict__ Wc, const float* __restrict__ bc,
                        const float* __restrict__ Wqkv, const float* __restrict__ bqkv) {
    int b = blockIdx.x, t = threadIdx.x;  // 256 threads
    __shared__ float cat[513];
    __shared__ float ve_s[Ec];
    __shared__ float q_s[Ec];
    __shared__ int red[8];

    float cap = g_cap[b];
    int cur = g_cur[b];
    float cnt = g_cnt[b];

    cat[t] = g_sumx[b][t] / cnt;                        // mean embed
    cat[256 + t] = x[((size_t)b * Nc + cur) * Ec + t];  // selected embed
    if (t == 0) cat[512] = cap;

    // mask: visited | demand > cap; depot masked while at depot
    int allm = 1;
    for (int n = t; n < Nc; n += 256) {
        int m = (g_visited[b][n] != 0) || (demand[(size_t)b * Nc + n] > cap);
        if (n == 0) m = (cur == 0) ? 1 : m;
        g_mask[b][n] = (unsigned char)m;
        allm &= m;
    }
    allm = __all_sync(0xffffffffu, allm);
    if ((t & 31) == 0) red[t >> 5] = allm;
    __syncthreads();
    if (t == 0) {
        int a = 1;
        for (int w = 0; w < 8; w++) a &= red[w];
        if (a) g_mask[b][0] = 0;  // unmask depot if everything is masked
    }

    // ve = cat @ Wc + bc
    float a = bc[t];
    for (int i = 0; i < 513; i++) a += cat[i] * Wc[i * Ec + t];
    ve_s[t] = a;
    __syncthreads();

    // q = ve @ Wq + bq   (Wq = Wqkv[:, 0:256])
    float qa = bqkv[t];
    for (int e = 0; e < Ec; e++) qa += ve_s[e] * Wqkv[e * 768 + t];
    q_s[t] = qa;
    __syncthreads();

    // qk[h][e] = scale * sum_dd q[h*32+dd] * Wk[e, h*32+dd]
    const float scale = 0.17677669529663687f;  // 1/sqrt(32)
    for (int r = 0; r < 8; r++) {
        int h = r, e = t;
        float s = 0.f;
        const float* w = Wqkv + e * 768 + 256 + h * 32;
        const float* qq = q_s + h * 32;
#pragma unroll
        for (int dd = 0; dd < 32; dd++) s += qq[dd] * w[dd];
        g_qk[b][h][e] = s * scale;
    }
    if (t < Hc) {
        float s = 0.f;
        for (int dd = 0; dd < 32; dd++) s += q_s[t * 32 + dd] * bqkv[256 + t * 32 + dd];
        g_sbias[b][t] = s * scale;
    }
}

// ---------------- K2: fused flash attention pass over x ----------------------
// grid (SEG, B), 256 threads. Each warp computes scores for its n-rows across
// all 8 heads, and owns online-softmax state + x-weighted accumulator of head w.
__global__ void __launch_bounds__(256, 2)
k_attn(const float* __restrict__ x) {
    int seg = blockIdx.x, b = blockIdx.y;
    int t = threadIdx.x, lane = t & 31, w = t >> 5;
    __shared__ float xs[SUBN * Ec];   // 32 KB
    __shared__ float ss[Hc * SUBN];   // scores -> p

    // cache this lane's slice of all 8 qk vectors: e = lane*8 + j
    float qkr[8][8];
#pragma unroll
    for (int h = 0; h < 8; h++)
#pragma unroll
        for (int j = 0; j < 8; j++) qkr[h][j] = g_qk[b][h][lane * 8 + j];
    float sb[8];
#pragma unroll
    for (int h = 0; h < 8; h++) sb[h] = g_sbias[b][h];

    float acc[8];
#pragma unroll
    for (int j = 0; j < 8; j++) acc[j] = 0.f;
    float mstate = NEG_BIG, lstate = 0.f;

    int n0 = seg * NSEG;
    for (int c = 0; c < NSEG / SUBN; c++) {
        int nb = n0 + c * SUBN;
        __syncthreads();  // protect xs/ss from previous iteration readers
        {   // stage 32 rows of x (32KB) coalesced
            const float4* src = (const float4*)(x + ((size_t)b * Nc + nb) * Ec);
            float4* dst = (float4*)xs;
#pragma unroll
            for (int i = 0; i < 8; i++) dst[t + 256 * i] = src[t + 256 * i];
        }
        __syncthreads();

        // scores: warp w handles n_local = w*4 .. w*4+3, all heads
#pragma unroll
        for (int i = 0; i < 4; i++) {
            int nl = w * 4 + i;
            float4 xv0 = ((const float4*)(xs + nl * Ec))[lane * 2];
            float4 xv1 = ((const float4*)(xs + nl * Ec))[lane * 2 + 1];
            float xr[8] = {xv0.x, xv0.y, xv0.z, xv0.w, xv1.x, xv1.y, xv1.z, xv1.w};
            float s[8];
#pragma unroll
            for (int h = 0; h < 8; h++) {
                float a = 0.f;
#pragma unroll
                for (int j = 0; j < 8; j++) a += qkr[h][j] * xr[j];
                s[h] = a;
            }
#pragma unroll
            for (int off = 16; off; off >>= 1)
#pragma unroll
                for (int h = 0; h < 8; h++)
                    s[h] += __shfl_xor_sync(0xffffffffu, s[h], off);
            if (lane < 8) {
                int gm = g_mask[b][nb + nl];
                ss[lane * SUBN + nl] = gm ? NEG_BIG : (s[lane] + sb[lane]);
            }
        }
        __syncthreads();

        // online softmax + acc update: warp w owns head w
        {
            float v = ss[w * SUBN + lane];
            float mx = v;
#pragma unroll
            for (int off = 16; off; off >>= 1)
                mx = fmaxf(mx, __shfl_xor_sync(0xffffffffu, mx, off));
            float mnew = fmaxf(mstate, mx);
            float alpha = (mstate > 0.5f * NEG_BIG) ? expf(mstate - mnew) : 0.f;
            float p = (v > 0.5f * NEG_BIG) ? expf(v - mnew) : 0.f;
            ss[w * SUBN + lane] = p;
            float ps = p;
#pragma unroll
            for (int off = 16; off; off >>= 1)
                ps += __shfl_xor_sync(0xffffffffu, ps, off);
            lstate = lstate * alpha + ps;
            mstate = mnew;
            __syncwarp();
#pragma unroll
            for (int j = 0; j < 8; j++) acc[j] *= alpha;
            for (int n = 0; n < SUBN; n++) {
                float pn = ss[w * SUBN + n];
                float4 xv0 = ((const float4*)(xs + n * Ec))[lane * 2];
                float4 xv1 = ((const float4*)(xs + n * Ec))[lane * 2 + 1];
                acc[0] += pn * xv0.x; acc[1] += pn * xv0.y;
                acc[2] += pn * xv0.z; acc[3] += pn * xv0.w;
                acc[4] += pn * xv1.x; acc[5] += pn * xv1.y;
                acc[6] += pn * xv1.z; acc[7] += pn * xv1.w;
            }
        }
    }
    // write partial for (b, seg, head=w)
    float* dst = &g_part[b][seg][w][0];
    if (lane == 0) { dst[0] = mstate; dst[1] = lstate; }
#pragma unroll
    for (int j = 0; j < 8; j++) dst[2 + lane * 8 + j] = acc[j];
}

// ---------------- K3: merge partials + projection chain ----------------------
__global__ void k_proj(const float* __restrict__ Wqkv, const float* __restrict__ bqkv,
                       const float* __restrict__ Wo, const float* __restrict__ bo,
                       const float* __restrict__ Wpq, const float* __restrict__ bpq,
                       const float* __restrict__ Wpk, const float* __restrict__ bpk) {
    int b = blockIdx.x, t = threadIdx.x;  // 256 threads
    __shared__ float ctxX[Hc][Ec];
    __shared__ float ctx_s[Ec];
    __shared__ float o_s[Ec];
    __shared__ float qp_s[Ec];
    __shared__ float red[8];

    for (int h = 0; h < Hc; h++) {
        float M = NEG_BIG;
        for (int s = 0; s < SEG; s++) M = fmaxf(M, g_part[b][s][h][0]);
        float L = 0.f, a = 0.f;
        for (int s = 0; s < SEG; s++) {
            float ms = g_part[b][s][h][0];
            float wgt = (ms > 0.5f * NEG_BIG) ? expf(ms - M) : 0.f;
            L += wgt * g_part[b][s][h][1];
            a += wgt * g_part[b][s][h][2 + t];
        }
        ctxX[h][t] = a / L;
    }
    __syncthreads();

    // ctx[j] = sum_e ctxX[h][e] * Wv[e, 512+j] + bv[j],  h = j/32
    {
        int h = t >> 5;
        float a = bqkv[512 + t];
        for (int e = 0; e < Ec; e++) a += ctxX[h][e] * Wqkv[e * 768 + 512 + t];
        ctx_s[t] = a;
    }
    __syncthreads();
    { float a = bo[t];  for (int i = 0; i < Ec; i++) a += ctx_s[i] * Wo[i * Ec + t]; o_s[t] = a; }
    __syncthreads();
    { float a = bpq[t]; for (int i = 0; i < Ec; i++) a += o_s[i] * Wpq[i * Ec + t]; qp_s[t] = a; }
    __syncthreads();
    { float a = 0.f;    for (int d = 0; d < Ec; d++) a += qp_s[d] * Wpk[t * Ec + d]; g_qpk[b][t] = a; }

    float ub = qp_s[t] * bpk[t];
#pragma unroll
    for (int off = 16; off; off >>= 1) ub += __shfl_xor_sync(0xffffffffu, ub, off);
    if ((t & 31) == 0) red[t >> 5] = ub;
    __syncthreads();
    if (t == 0) {
        float s = 0.f;
        for (int w = 0; w < 8; w++) s += red[w];
        g_ub[b] = s;
    }
}

// ---------------- K4: pointer logits u = 10*tanh(qpk . x + ub), masked -------
__global__ void k_point(const float* __restrict__ x) {
    int seg = blockIdx.x, b = blockIdx.y;
    int t = threadIdx.x, lane = t & 31, w = t >> 5;
    __shared__ float qs[Ec];
    if (t < Ec) qs[t] = g_qpk[b][t];
    __syncthreads();
    float ub = g_ub[b];
    float q0[8];
#pragma unroll
    for (int j = 0; j < 8; j++) q0[j] = qs[lane * 8 + j];
    int nbase = seg * 256 + w * 32;
    for (int i = 0; i < 32; i++) {
        int n = nbase + i;
        const float4* xr = (const float4*)(x + ((size_t)b * Nc + n) * Ec);
        float4 a0 = xr[lane * 2], a1 = xr[lane * 2 + 1];
        float s = q0[0] * a0.x + q0[1] * a0.y + q0[2] * a0.z + q0[3] * a0.w
                + q0[4] * a1.x + q0[5] * a1.y + q0[6] * a1.z + q0[7] * a1.w;
#pragma unroll
        for (int off = 16; off; off >>= 1) s += __shfl_xor_sync(0xffffffffu, s, off);
        if (lane == 0) {
            g_u[b][n] = g_mask[b][n] ? NEG_BIG : CLIPC * tanhf(s + ub);
        }
    }
}

// ---------------- K5: softmax + argmax + state update + outputs --------------
__global__ void k_select(const float* __restrict__ x, const float* __restrict__ demand,
                         float* __restrict__ out, int t_step, int write_route) {
    int b = blockIdx.x, t = threadIdx.x;  // 1024 threads
    __shared__ float sval[32];
    __shared__ int sidx[32];
    __shared__ float ssum[32];
    __shared__ int s_node;
    __shared__ float s_max;

    float v = g_u[b][t];
    int idx = t;
#pragma unroll
    for (int off = 16; off; off >>= 1) {
        float ov = __shfl_xor_sync(0xffffffffu, v, off);
        int oi = __shfl_xor_sync(0xffffffffu, idx, off);
        if (ov > v || (ov == v && oi < idx)) { v = ov; idx = oi; }
    }
    if ((t & 31) == 0) { sval[t >> 5] = v; sidx[t >> 5] = idx; }
    __syncthreads();
    if (t < 32) {
        v = sval[t]; idx = sidx[t];
#pragma unroll
        for (int off = 16; off; off >>= 1) {
            float ov = __shfl_xor_sync(0xffffffffu, v, off);
            int oi = __shfl_xor_sync(0xffffffffu, idx, off);
            if (ov > v || (ov == v && oi < idx)) { v = ov; idx = oi; }
        }
        if (t == 0) { s_node = idx; s_max = v; }
    }
    __syncthreads();
    float mx = s_max;
    int node = s_node;
    float u = g_u[b][t];
    float p = expf(u - mx);  // masked entries underflow to exactly 0

    float s = p;
#pragma unroll
    for (int off = 16; off; off >>= 1) s += __shfl_xor_sync(0xffffffffu, s, off);
    if ((t & 31) == 0) ssum[t >> 5] = s;
    __syncthreads();
    if (t < 32) {
        s = ssum[t];
#pragma unroll
        for (int off = 16; off; off >>= 1) s += __shfl_xor_sync(0xffffffffu, s, off);
        if (t == 0) ssum[0] = s;
    }
    __syncthreads();
    out[(size_t)t_step * Bc * Nc + (size_t)b * Nc + t] = p / ssum[0];

    if (t == 0 && write_route)
        out[(size_t)Tc * Bc * Nc + (size_t)t_step * Bc + b] = (float)node;
    if (t == 0) {
        g_cap[b] = g_cap[b] - demand[(size_t)b * Nc + node];
        g_cur[b] = node;
    }
    if (t < Ec) {
        if (node != 0 && g_visited[b][node] == 0)
            g_sumx[b][t] -= x[((size_t)b * Nc + node) * Ec + t];
    }
    __syncthreads();
    if (t == 0) {
        if (node != 0 && g_visited[b][node] == 0) {
            g_visited[b][node] = 1;
            g_cnt[b] -= 1.f;
        }
    }
}

// ---------------- launch ------------------------------------------------------
extern "C" void kernel_launch(void* const* d_in, const int* in_sizes, int n_in,
                              void* d_out, int out_size) {
    const float* x      = (const float*)d_in[0];
    const float* demand = (const float*)d_in[1];
    const float* cap0   = (const float*)d_in[2];
    const float* Wc     = (const float*)d_in[3];
    const float* bc     = (const float*)d_in[4];
    const float* Wqkv   = (const float*)d_in[5];
    const float* bqkv   = (const float*)d_in[6];
    const float* Wo     = (const float*)d_in[7];
    const float* bo     = (const float*)d_in[8];
    const float* Wpq    = (const float*)d_in[9];
    const float* bpq    = (const float*)d_in[10];
    const float* Wpk    = (const float*)d_in[11];
    const float* bpk    = (const float*)d_in[12];
    float* out = (float*)d_out;
    int write_route = (out_size > Tc * Bc * Nc) ? 1 : 0;

    k_init<<<Bc, 256>>>(x, cap0);
    for (int t = 0; t < Tc; t++) {
        k_state<<<Bc, 256>>>(x, demand, Wc, bc, Wqkv, bqkv);
        k_attn<<<dim3(SEG, Bc), 256>>>(x);
        k_proj<<<Bc, 256>>>(Wqkv, bqkv, Wo, bo, Wpq, bpq, Wpk, bpk);
        k_point<<<dim3(SEG, Bc), 256>>>(x);
        k_select<<<Bc, 1024>>>(x, demand, out, t, write_route);
    }
}

// round 3
// speedup vs baseline: 1.0010x; 1.0010x over previous
#include <cuda_runtime.h>
#include <math.h>

#define Bc 256
#define Nc 1024
#define Ec 256
#define Hc 8
#define Tc 64
#define SEG 4
#define NSEG 256        // N / SEG
#define SUBN 32         // n rows staged in smem per chunk
#define NEG_BIG (-1e30f)
#define CLIPC 10.0f

// ---------------- persistent device state (no allocs allowed) ----------------
__device__ float g_sumx[Bc][Ec];          // running sum of unvisited x
__device__ float g_cnt[Bc];               // unvisited count
__device__ float g_cap[Bc];               // remaining capacity
__device__ int   g_cur[Bc];               // current node
__device__ unsigned char g_visited[Bc][Nc];
__device__ unsigned char g_mask[Bc][Nc];
__device__ float g_qk[Bc][Hc][Ec];        // folded query-key vectors (incl. scale)
__device__ float g_sbias[Bc][Hc];         // scale * q . bk
__device__ float g_part[Bc][SEG][Hc][Ec + 2];  // flash partials: m, l, acc[256]
__device__ float g_qpk[Bc][Ec];           // pointer query folded through Wpk
__device__ float g_ub[Bc];                // qp . bpk
__device__ float g_u[Bc][Nc];             // masked pointer logits

// ---------------- init: per-launch state reset + column sums of x ------------
__global__ void k_init(const float* __restrict__ x, const float* __restrict__ cap0) {
    int b = blockIdx.x, t = threadIdx.x;  // 256 threads
    const float* xb = x + (size_t)b * Nc * Ec;
    float s = 0.f;
    for (int n = 0; n < Nc; n++) s += xb[(size_t)n * Ec + t];
    g_sumx[b][t] = s;
    for (int i = t; i < Nc; i += 256) g_visited[b][i] = 0;
    if (t == 0) {
        g_cnt[b] = (float)Nc;
        g_cap[b] = cap0[b];
        g_cur[b] = 0;
    }
}

// ---------------- K1: mask + vehicle embed + q + folded qk -------------------
__global__ void k_state(const float* __restrict__ x, const float* __restrict__ demand,
                        const float* __restrict__ Wc, const float* __restrict__ bc,
                        const float* __restrict__ Wqkv, const float* __restrict__ bqkv) {
    int b = blockIdx.x, t = threadIdx.x;  // 256 threads
    __shared__ float cat[513];
    __shared__ float ve_s[Ec];
    __shared__ float q_s[Ec];
    __shared__ int red[8];

    float cap = g_cap[b];
    int cur = g_cur[b];
    float cnt = g_cnt[b];

    cat[t] = g_sumx[b][t] / cnt;                        // mean embed
    cat[256 + t] = x[((size_t)b * Nc + cur) * Ec + t];  // selected embed
    if (t == 0) cat[512] = cap;

    // mask: visited | demand > cap; depot masked while at depot
    int allm = 1;
    for (int n = t; n < Nc; n += 256) {
        int m = (g_visited[b][n] != 0) || (demand[(size_t)b * Nc + n] > cap);
        if (n == 0) m = (cur == 0) ? 1 : m;
        g_mask[b][n] = (unsigned char)m;
        allm &= m;
    }
    allm = __all_sync(0xffffffffu, allm);
    if ((t & 31) == 0) red[t >> 5] = allm;
    __syncthreads();
    if (t == 0) {
        int a = 1;
        for (int w = 0; w < 8; w++) a &= red[w];
        if (a) g_mask[b][0] = 0;  // unmask depot if everything is masked
    }

    // ve = cat @ Wc + bc
    float a = bc[t];
    for (int i = 0; i < 513; i++) a += cat[i] * Wc[i * Ec + t];
    ve_s[t] = a;
    __syncthreads();

    // q = ve @ Wq + bq   (Wq = Wqkv[:, 0:256])
    float qa = bqkv[t];
    for (int e = 0; e < Ec; e++) qa += ve_s[e] * Wqkv[e * 768 + t];
    q_s[t] = qa;
    __syncthreads();

    // qk[h][e] = scale * sum_dd q[h*32+dd] * Wk[e, h*32+dd]
    const float scale = 0.17677669529663687f;  // 1/sqrt(32)
    for (int r = 0; r < 8; r++) {
        int h = r, e = t;
        float s = 0.f;
        const float* w = Wqkv + e * 768 + 256 + h * 32;
        const float* qq = q_s + h * 32;
#pragma unroll
        for (int dd = 0; dd < 32; dd++) s += qq[dd] * w[dd];
        g_qk[b][h][e] = s * scale;
    }
    if (t < Hc) {
        float s = 0.f;
        for (int dd = 0; dd < 32; dd++) s += q_s[t * 32 + dd] * bqkv[256 + t * 32 + dd];
        g_sbias[b][t] = s * scale;
    }
}

// ---------------- K2: fused flash attention pass over x ----------------------
// grid (SEG, B), 256 threads. Each warp computes scores for its n-rows across
// all 8 heads, and owns online-softmax state + x-weighted accumulator of head w.
__global__ void __launch_bounds__(256, 2)
k_attn(const float* __restrict__ x) {
    int seg = blockIdx.x, b = blockIdx.y;
    int t = threadIdx.x, lane = t & 31, w = t >> 5;
    __shared__ float xs[SUBN * Ec];   // 32 KB
    __shared__ float ss[Hc * SUBN];   // scores -> p

    // cache this lane's slice of all 8 qk vectors: e = lane*8 + j
    float qkr[8][8];
#pragma unroll
    for (int h = 0; h < 8; h++)
#pragma unroll
        for (int j = 0; j < 8; j++) qkr[h][j] = g_qk[b][h][lane * 8 + j];
    float sb[8];
#pragma unroll
    for (int h = 0; h < 8; h++) sb[h] = g_sbias[b][h];

    float acc[8];
#pragma unroll
    for (int j = 0; j < 8; j++) acc[j] = 0.f;
    float mstate = NEG_BIG, lstate = 0.f;

    int n0 = seg * NSEG;
    for (int c = 0; c < NSEG / SUBN; c++) {
        int nb = n0 + c * SUBN;
        __syncthreads();  // protect xs/ss from previous iteration readers
        {   // stage 32 rows of x (32KB) coalesced
            const float4* src = (const float4*)(x + ((size_t)b * Nc + nb) * Ec);
            float4* dst = (float4*)xs;
#pragma unroll
            for (int i = 0; i < 8; i++) dst[t + 256 * i] = src[t + 256 * i];
        }
        __syncthreads();

        // scores: warp w handles n_local = w*4 .. w*4+3, all heads
#pragma unroll
        for (int i = 0; i < 4; i++) {
            int nl = w * 4 + i;
            float4 xv0 = ((const float4*)(xs + nl * Ec))[lane * 2];
            float4 xv1 = ((const float4*)(xs + nl * Ec))[lane * 2 + 1];
            float xr[8] = {xv0.x, xv0.y, xv0.z, xv0.w, xv1.x, xv1.y, xv1.z, xv1.w};
            float s[8];
#pragma unroll
            for (int h = 0; h < 8; h++) {
                float a = 0.f;
#pragma unroll
                for (int j = 0; j < 8; j++) a += qkr[h][j] * xr[j];
                s[h] = a;
            }
#pragma unroll
            for (int off = 16; off; off >>= 1)
#pragma unroll
                for (int h = 0; h < 8; h++)
                    s[h] += __shfl_xor_sync(0xffffffffu, s[h], off);
            if (lane < 8) {
                int gm = g_mask[b][nb + nl];
                ss[lane * SUBN + nl] = gm ? NEG_BIG : (s[lane] + sb[lane]);
            }
        }
        __syncthreads();

        // online softmax + acc update: warp w owns head w
        {
            float v = ss[w * SUBN + lane];
            float mx = v;
#pragma unroll
            for (int off = 16; off; off >>= 1)
                mx = fmaxf(mx, __shfl_xor_sync(0xffffffffu, mx, off));
            float mnew = fmaxf(mstate, mx);
            float alpha = (mstate > 0.5f * NEG_BIG) ? expf(mstate - mnew) : 0.f;
            float p = (v > 0.5f * NEG_BIG) ? expf(v - mnew) : 0.f;
            ss[w * SUBN + lane] = p;
            float ps = p;
#pragma unroll
            for (int off = 16; off; off >>= 1)
                ps += __shfl_xor_sync(0xffffffffu, ps, off);
            lstate = lstate * alpha + ps;
            mstate = mnew;
            __syncwarp();
#pragma unroll
            for (int j = 0; j < 8; j++) acc[j] *= alpha;
            for (int n = 0; n < SUBN; n++) {
                float pn = ss[w * SUBN + n];
                float4 xv0 = ((const float4*)(xs + n * Ec))[lane * 2];
                float4 xv1 = ((const float4*)(xs + n * Ec))[lane * 2 + 1];
                acc[0] += pn * xv0.x; acc[1] += pn * xv0.y;
                acc[2] += pn * xv0.z; acc[3] += pn * xv0.w;
                acc[4] += pn * xv1.x; acc[5] += pn * xv1.y;
                acc[6] += pn * xv1.z; acc[7] += pn * xv1.w;
            }
        }
    }
    // write partial for (b, seg, head=w)
    float* dst = &g_part[b][seg][w][0];
    if (lane == 0) { dst[0] = mstate; dst[1] = lstate; }
#pragma unroll
    for (int j = 0; j < 8; j++) dst[2 + lane * 8 + j] = acc[j];
}

// ---------------- K3: merge partials + projection chain ----------------------
__global__ void k_proj(const float* __restrict__ Wqkv, const float* __restrict__ bqkv,
                       const float* __restrict__ Wo, const float* __restrict__ bo,
                       const float* __restrict__ Wpq, const float* __restrict__ bpq,
                       const float* __restrict__ Wpk, const float* __restrict__ bpk) {
    int b = blockIdx.x, t = threadIdx.x;  // 256 threads
    __shared__ float ctxX[Hc][Ec];
    __shared__ float ctx_s[Ec];
    __shared__ float o_s[Ec];
    __shared__ float qp_s[Ec];
    __shared__ float red[8];

    for (int h = 0; h < Hc; h++) {
        float M = NEG_BIG;
        for (int s = 0; s < SEG; s++) M = fmaxf(M, g_part[b][s][h][0]);
        float L = 0.f, a = 0.f;
        for (int s = 0; s < SEG; s++) {
            float ms = g_part[b][s][h][0];
            float wgt = (ms > 0.5f * NEG_BIG) ? expf(ms - M) : 0.f;
            L += wgt * g_part[b][s][h][1];
            a += wgt * g_part[b][s][h][2 + t];
        }
        ctxX[h][t] = a / L;
    }
    __syncthreads();

    // ctx[j] = sum_e ctxX[h][e] * Wv[e, 512+j] + bv[j],  h = j/32
    {
        int h = t >> 5;
        float a = bqkv[512 + t];
        for (int e = 0; e < Ec; e++) a += ctxX[h][e] * Wqkv[e * 768 + 512 + t];
        ctx_s[t] = a;
    }
    __syncthreads();
    { float a = bo[t];  for (int i = 0; i < Ec; i++) a += ctx_s[i] * Wo[i * Ec + t]; o_s[t] = a; }
    __syncthreads();
    { float a = bpq[t]; for (int i = 0; i < Ec; i++) a += o_s[i] * Wpq[i * Ec + t]; qp_s[t] = a; }
    __syncthreads();
    { float a = 0.f;    for (int d = 0; d < Ec; d++) a += qp_s[d] * Wpk[t * Ec + d]; g_qpk[b][t] = a; }

    float ub = qp_s[t] * bpk[t];
#pragma unroll
    for (int off = 16; off; off >>= 1) ub += __shfl_xor_sync(0xffffffffu, ub, off);
    if ((t & 31) == 0) red[t >> 5] = ub;
    __syncthreads();
    if (t == 0) {
        float s = 0.f;
        for (int w = 0; w < 8; w++) s += red[w];
        g_ub[b] = s;
    }
}

// ---------------- K4: pointer logits u = 10*tanh(qpk . x + ub), masked -------
__global__ void k_point(const float* __restrict__ x) {
    int seg = blockIdx.x, b = blockIdx.y;
    int t = threadIdx.x, lane = t & 31, w = t >> 5;
    __shared__ float qs[Ec];
    if (t < Ec) qs[t] = g_qpk[b][t];
    __syncthreads();
    float ub = g_ub[b];
    float q0[8];
#pragma unroll
    for (int j = 0; j < 8; j++) q0[j] = qs[lane * 8 + j];
    int nbase = seg * 256 + w * 32;
    for (int i = 0; i < 32; i++) {
        int n = nbase + i;
        const float4* xr = (const float4*)(x + ((size_t)b * Nc + n) * Ec);
        float4 a0 = xr[lane * 2], a1 = xr[lane * 2 + 1];
        float s = q0[0] * a0.x + q0[1] * a0.y + q0[2] * a0.z + q0[3] * a0.w
                + q0[4] * a1.x + q0[5] * a1.y + q0[6] * a1.z + q0[7] * a1.w;
#pragma unroll
        for (int off = 16; off; off >>= 1) s += __shfl_xor_sync(0xffffffffu, s, off);
        if (lane == 0) {
            g_u[b][n] = g_mask[b][n] ? NEG_BIG : CLIPC * tanhf(s + ub);
        }
    }
}

// ---------------- K5: softmax + argmax + state update + outputs --------------
__global__ void k_select(const float* __restrict__ x, const float* __restrict__ demand,
                         float* __restrict__ out, int t_step, int write_route) {
    int b = blockIdx.x, t = threadIdx.x;  // 1024 threads
    __shared__ float sval[32];
    __shared__ int sidx[32];
    __shared__ float ssum[32];
    __shared__ int s_node;
    __shared__ float s_max;

    float v = g_u[b][t];
    int idx = t;
#pragma unroll
    for (int off = 16; off; off >>= 1) {
        float ov = __shfl_xor_sync(0xffffffffu, v, off);
        int oi = __shfl_xor_sync(0xffffffffu, idx, off);
        if (ov > v || (ov == v && oi < idx)) { v = ov; idx = oi; }
    }
    if ((t & 31) == 0) { sval[t >> 5] = v; sidx[t >> 5] = idx; }
    __syncthreads();
    if (t < 32) {
        v = sval[t]; idx = sidx[t];
#pragma unroll
        for (int off = 16; off; off >>= 1) {
            float ov = __shfl_xor_sync(0xffffffffu, v, off);
            int oi = __shfl_xor_sync(0xffffffffu, idx, off);
            if (ov > v || (ov == v && oi < idx)) { v = ov; idx = oi; }
        }
        if (t == 0) { s_node = idx; s_max = v; }
    }
    __syncthreads();
    float mx = s_max;
    int node = s_node;
    float u = g_u[b][t];
    float p = expf(u - mx);  // masked entries underflow to exactly 0

    float s = p;
#pragma unroll
    for (int off = 16; off; off >>= 1) s += __shfl_xor_sync(0xffffffffu, s, off);
    if ((t & 31) == 0) ssum[t >> 5] = s;
    __syncthreads();
    if (t < 32) {
        s = ssum[t];
#pragma unroll
        for (int off = 16; off; off >>= 1) s += __shfl_xor_sync(0xffffffffu, s, off);
        if (t == 0) ssum[0] = s;
    }
    __syncthreads();
    out[(size_t)t_step * Bc * Nc + (size_t)b * Nc + t] = p / ssum[0];

    if (t == 0 && write_route)
        out[(size_t)Tc * Bc * Nc + (size_t)t_step * Bc + b] = (float)node;
    if (t == 0) {
        g_cap[b] = g_cap[b] - demand[(size_t)b * Nc + node];
        g_cur[b] = node;
    }
    if (t < Ec) {
        if (node != 0 && g_visited[b][node] == 0)
            g_sumx[b][t] -= x[((size_t)b * Nc + node) * Ec + t];
    }
    __syncthreads();
    if (t == 0) {
        if (node != 0 && g_visited[b][node] == 0) {
            g_visited[b][node] = 1;
            g_cnt[b] -= 1.f;
        }
    }
}

// ---------------- launch ------------------------------------------------------
extern "C" void kernel_launch(void* const* d_in, const int* in_sizes, int n_in,
                              void* d_out, int out_size) {
    const float* x      = (const float*)d_in[0];
    const float* demand = (const float*)d_in[1];
    const float* cap0   = (const float*)d_in[2];
    const float* Wc     = (const float*)d_in[3];
    const float* bc     = (const float*)d_in[4];
    const float* Wqkv   = (const float*)d_in[5];
    const float* bqkv   = (const float*)d_in[6];
    const float* Wo     = (const float*)d_in[7];
    const float* bo     = (const float*)d_in[8];
    const float* Wpq    = (const float*)d_in[9];
    const float* bpq    = (const float*)d_in[10];
    const float* Wpk    = (const float*)d_in[11];
    const float* bpk    = (const float*)d_in[12];
    float* out = (float*)d_out;
    int write_route = (out_size > Tc * Bc * Nc) ? 1 : 0;

    k_init<<<Bc, 256>>>(x, cap0);
    for (int t = 0; t < Tc; t++) {
        k_state<<<Bc, 256>>>(x, demand, Wc, bc, Wqkv, bqkv);
        k_attn<<<dim3(SEG, Bc), 256>>>(x);
        k_proj<<<Bc, 256>>>(Wqkv, bqkv, Wo, bo, Wpq, bpq, Wpk, bpk);
        k_point<<<dim3(SEG, Bc), 256>>>(x);
        k_select<<<Bc, 1024>>>(x, demand, out, t, write_route);
    }
}

// round 4
// speedup vs baseline: 1.3728x; 1.3714x over previous
#include <cuda_runtime.h>
#include <math.h>

#define Bc 256
#define Nc 1024
#define Ec 256
#define Hc 8
#define Tc 64
#define SEG 4
#define NSEG 256
#define SUBN 32
#define NEG_BIG (-1e30f)
#define CLIPC 10.0f

#define K1 544      // padded K for gemm1 (used: 514)
#define N1 2176     // padded N for gemm1 (used: 2056 = 8*256 qk + 8 sbias)
#define K2 2080     // padded K for gemm2 (used: 2049 = 8*256 ctxX + 1 homog)
#define N2 288      // padded N for gemm2 (used: 257 = 256 qpk + 1 ub)

// ---------------- persistent device state ----------------
__device__ float g_sumx[Bc][Ec];
__device__ float g_cnt[Bc];
__device__ float g_cap[Bc];
__device__ int   g_cur[Bc];
__device__ unsigned char g_visited[Bc][Nc];
__device__ unsigned char g_mask[Bc][Nc];
__device__ float g_part[Bc][SEG][Hc][Ec + 2];
__device__ float g_u[Bc][Nc];

// folded weights / activations
__device__ float g_A1[514][256];        // [Wc@Wq ; bc@Wq+bq]
__device__ float g_WkT[256][256];       // Wk transposed
__device__ float g_Wbig[K1][N1];        // cat -> (qk flat, sbias)
__device__ float g_cat[Bc][K1];
__device__ float g_qkflat[Bc][N1];
__device__ float g_T2ext[257][256];     // [Wo@Wpq ; bo@Wpq+bpq]
__device__ float g_WpkT[256][256];
__device__ float g_T3ext[257][288];     // [T2@WpkT | T2@bpk]
__device__ float g_G[K2][N2];           // ctxX -> (qpk, ub)
__device__ float g_ctxA[Bc][K2];
__device__ float g_qpkpart[8][Bc][N2];

// ---------------- init ----------------
__global__ void k_init(const float* __restrict__ x, const float* __restrict__ cap0) {
    int b = blockIdx.x, t = threadIdx.x;
    const float* xb = x + (size_t)b * Nc * Ec;
    float s = 0.f;
    for (int n = 0; n < Nc; n++) s += xb[(size_t)n * Ec + t];
    g_sumx[b][t] = s;
    for (int i = t; i < Nc; i += 256) g_visited[b][i] = 0;
    if (t == 0) {
        g_cnt[b] = (float)Nc;
        g_cap[b] = cap0[b];
        g_cur[b] = 0;
    }
}

// ---------------- precompute (once per launch) ----------------
__global__ void pZero() {
    int idx = blockIdx.x * 256 + threadIdx.x;
    float* w = &g_Wbig[0][0];
    for (int i = idx; i < K1 * N1; i += gridDim.x * 256) w[i] = 0.f;
    float* g = &g_G[0][0];
    for (int i = idx; i < K2 * N2; i += gridDim.x * 256) g[i] = 0.f;
}

__global__ void pA1(const float* __restrict__ Wc, const float* __restrict__ bc,
                    const float* __restrict__ Wqkv, const float* __restrict__ bqkv) {
    int i = blockIdx.x, t = threadIdx.x;  // 514 blocks
    __shared__ float wrow[256];
    wrow[t] = (i < 513) ? Wc[i * 256 + t] : bc[t];
    __syncthreads();
    float s = (i == 513) ? bqkv[t] : 0.f;
    for (int e = 0; e < 256; e++) s += wrow[e] * Wqkv[e * 768 + t];
    g_A1[i][t] = s;
}

__global__ void pWkT(const float* __restrict__ Wqkv) {
    int d = blockIdx.x, e = threadIdx.x;
    g_WkT[d][e] = Wqkv[e * 768 + 256 + d];
}

__global__ void pWbig(const float* __restrict__ bqkv) {
    int i = blockIdx.x, e = threadIdx.x;  // 514 blocks
    __shared__ float a1[256];
    a1[e] = g_A1[i][e];
    __syncthreads();
    const float scale = 0.17677669529663687f;
#pragma unroll
    for (int h = 0; h < 8; h++) {
        float s = 0.f;
#pragma unroll
        for (int dd = 0; dd < 32; dd++) s += a1[h * 32 + dd] * g_WkT[h * 32 + dd][e];
        g_Wbig[i][h * 256 + e] = scale * s;
    }
    if (e < 8) {
        float s = 0.f;
        for (int dd = 0; dd < 32; dd++) s += a1[e * 32 + dd] * bqkv[256 + e * 32 + dd];
        g_Wbig[i][2048 + e] = scale * s;
    }
}

__global__ void pT2(const float* __restrict__ Wo, const float* __restrict__ bo,
                    const float* __restrict__ Wpq, const float* __restrict__ bpq) {
    int i = blockIdx.x, t = threadIdx.x;  // 257 blocks
    __shared__ float wrow[256];
    wrow[t] = (i < 256) ? Wo[i * 256 + t] : bo[t];
    __syncthreads();
    float s = (i == 256) ? bpq[t] : 0.f;
    for (int k = 0; k < 256; k++) s += wrow[k] * Wpq[k * 256 + t];
    g_T2ext[i][t] = s;
}

__global__ void pWpkT(const float* __restrict__ Wpk) {
    int j2 = blockIdx.x, d = threadIdx.x;
    g_WpkT[j2][d] = Wpk[d * 256 + j2];
}

__global__ void pT3(const float* __restrict__ bpk) {
    int j = blockIdx.x, t = threadIdx.x;  // 257 blocks, 288 threads
    __shared__ float t2[256];
    if (t < 256) t2[t] = g_T2ext[j][t];
    __syncthreads();
    if (t < 256) {
        float s = 0.f;
        for (int k = 0; k < 256; k++) s += t2[k] * g_WpkT[k][t];
        g_T3ext[j][t] = s;
    } else if (t == 256) {
        float s = 0.f;
        for (int k = 0; k < 256; k++) s += t2[k] * bpk[k];
        g_T3ext[j][256] = s;
    }
}

__global__ void pG(const float* __restrict__ Wqkv, const float* __restrict__ bqkv) {
    int he = blockIdx.x, t = threadIdx.x;  // 2049 blocks, 288 threads
    __shared__ float sw[256];
    if (he < 2048) {
        int h = he >> 8, e = he & 255;
        if (t < 32) sw[t] = Wqkv[e * 768 + 512 + h * 32 + t];
        __syncthreads();
        if (t < 257) {
            float s = 0.f;
            int jb = h * 32;
#pragma unroll
            for (int jl = 0; jl < 32; jl++) s += sw[jl] * g_T3ext[jb + jl][t];
            g_G[he][t] = s;
        }
    } else {
        if (t < 256) sw[t] = bqkv[512 + t];
        __syncthreads();
        if (t < 257) {
            float s = g_T3ext[256][t];
            for (int j = 0; j < 256; j++) s += sw[j] * g_T3ext[j][t];
            g_G[2048][t] = s;
        }
    }
}

// ---------------- per-step K1: mask + cat build (lite) ----------------
__global__ void k_state(const float* __restrict__ x, const float* __restrict__ demand) {
    int b = blockIdx.x, t = threadIdx.x;
    __shared__ int red[8];
    float cap = g_cap[b];
    int cur = g_cur[b];
    float cnt = g_cnt[b];
    g_cat[b][t] = g_sumx[b][t] / cnt;
    g_cat[b][256 + t] = x[((size_t)b * Nc + cur) * Ec + t];
    if (t == 0) { g_cat[b][512] = cap; g_cat[b][513] = 1.f; }
    if (t < 30) g_cat[b][514 + t] = 0.f;
    int allm = 1;
    for (int n = t; n < Nc; n += 256) {
        int m = (g_visited[b][n] != 0) || (demand[(size_t)b * Nc + n] > cap);
        if (n == 0) m = (cur == 0) ? 1 : m;
        g_mask[b][n] = (unsigned char)m;
        allm &= m;
    }
    allm = __all_sync(0xffffffffu, allm);
    if ((t & 31) == 0) red[t >> 5] = allm;
    __syncthreads();
    if (t == 0) {
        int a = 1;
        for (int w = 0; w < 8; w++) a &= red[w];
        if (a) g_mask[b][0] = 0;
    }
}

// ---------------- GEMM1: qkflat = cat @ Wbig ----------------
__global__ void __launch_bounds__(256) k_gemm1() {
    int n0 = blockIdx.x * 128, m0 = blockIdx.y * 32;
    int t = threadIdx.x, tx = t & 31, ty = t >> 5;
    __shared__ __align__(16) float As[32][33];
    __shared__ __align__(16) float Bs[32][128];
    float acc[4][4] = {};
    for (int k0 = 0; k0 < K1; k0 += 32) {
#pragma unroll
        for (int l = 0; l < 4; l++) {
            int idx = t + 256 * l;
            As[idx >> 5][idx & 31] = g_cat[m0 + (idx >> 5)][k0 + (idx & 31)];
        }
#pragma unroll
        for (int l = 0; l < 4; l++) {
            int idx = t + 256 * l;
            int r = idx >> 5, c = idx & 31;
            *(float4*)&Bs[r][c * 4] = *(const float4*)&g_Wbig[k0 + r][n0 + c * 4];
        }
        __syncthreads();
#pragma unroll
        for (int kk = 0; kk < 32; kk++) {
            float a0 = As[ty * 4 + 0][kk], a1 = As[ty * 4 + 1][kk];
            float a2 = As[ty * 4 + 2][kk], a3 = As[ty * 4 + 3][kk];
            float4 bv = *(const float4*)&Bs[kk][tx * 4];
            acc[0][0] += a0 * bv.x; acc[0][1] += a0 * bv.y; acc[0][2] += a0 * bv.z; acc[0][3] += a0 * bv.w;
            acc[1][0] += a1 * bv.x; acc[1][1] += a1 * bv.y; acc[1][2] += a1 * bv.z; acc[1][3] += a1 * bv.w;
            acc[2][0] += a2 * bv.x; acc[2][1] += a2 * bv.y; acc[2][2] += a2 * bv.z; acc[2][3] += a2 * bv.w;
            acc[3][0] += a3 * bv.x; acc[3][1] += a3 * bv.y; acc[3][2] += a3 * bv.z; acc[3][3] += a3 * bv.w;
        }
        __syncthreads();
    }
#pragma unroll
    for (int i = 0; i < 4; i++) {
        float4 v = make_float4(acc[i][0], acc[i][1], acc[i][2], acc[i][3]);
        *(float4*)&g_qkflat[m0 + ty * 4 + i][n0 + tx * 4] = v;
    }
}

// ---------------- K2: fused flash attention over x ----------------
__global__ void __launch_bounds__(256, 2)
k_attn(const float* __restrict__ x) {
    int seg = blockIdx.x, b = blockIdx.y;
    int t = threadIdx.x, lane = t & 31, w = t >> 5;
    __shared__ float xs[SUBN * Ec];
    __shared__ float ss[Hc * SUBN];

    float qkr[8][8];
#pragma unroll
    for (int h = 0; h < 8; h++)
#pragma unroll
        for (int j = 0; j < 8; j++) qkr[h][j] = g_qkflat[b][h * 256 + lane * 8 + j];
    float sb[8];
#pragma unroll
    for (int h = 0; h < 8; h++) sb[h] = g_qkflat[b][2048 + h];

    float acc[8];
#pragma unroll
    for (int j = 0; j < 8; j++) acc[j] = 0.f;
    float mstate = NEG_BIG, lstate = 0.f;

    int n0 = seg * NSEG;
    for (int c = 0; c < NSEG / SUBN; c++) {
        int nb = n0 + c * SUBN;
        __syncthreads();
        {
            const float4* src = (const float4*)(x + ((size_t)b * Nc + nb) * Ec);
            float4* dst = (float4*)xs;
#pragma unroll
            for (int i = 0; i < 8; i++) dst[t + 256 * i] = src[t + 256 * i];
        }
        __syncthreads();

#pragma unroll
        for (int i = 0; i < 4; i++) {
            int nl = w * 4 + i;
            float4 xv0 = ((const float4*)(xs + nl * Ec))[lane * 2];
            float4 xv1 = ((const float4*)(xs + nl * Ec))[lane * 2 + 1];
            float xr[8] = {xv0.x, xv0.y, xv0.z, xv0.w, xv1.x, xv1.y, xv1.z, xv1.w};
            float s[8];
#pragma unroll
            for (int h = 0; h < 8; h++) {
                float a = 0.f;
#pragma unroll
                for (int j = 0; j < 8; j++) a += qkr[h][j] * xr[j];
                s[h] = a;
            }
#pragma unroll
            for (int off = 16; off; off >>= 1)
#pragma unroll
                for (int h = 0; h < 8; h++)
                    s[h] += __shfl_xor_sync(0xffffffffu, s[h], off);
            if (lane < 8) {
                int gm = g_mask[b][nb + nl];
                ss[lane * SUBN + nl] = gm ? NEG_BIG : (s[lane] + sb[lane]);
            }
        }
        __syncthreads();

        {
            float v = ss[w * SUBN + lane];
            float mx = v;
#pragma unroll
            for (int off = 16; off; off >>= 1)
                mx = fmaxf(mx, __shfl_xor_sync(0xffffffffu, mx, off));
            float mnew = fmaxf(mstate, mx);
            float alpha = (mstate > 0.5f * NEG_BIG) ? expf(mstate - mnew) : 0.f;
            float p = (v > 0.5f * NEG_BIG) ? expf(v - mnew) : 0.f;
            ss[w * SUBN + lane] = p;
            float ps = p;
#pragma unroll
            for (int off = 16; off; off >>= 1)
                ps += __shfl_xor_sync(0xffffffffu, ps, off);
            lstate = lstate * alpha + ps;
            mstate = mnew;
            __syncwarp();
#pragma unroll
            for (int j = 0; j < 8; j++) acc[j] *= alpha;
            for (int n = 0; n < SUBN; n++) {
                float pn = ss[w * SUBN + n];
                float4 xv0 = ((const float4*)(xs + n * Ec))[lane * 2];
                float4 xv1 = ((const float4*)(xs + n * Ec))[lane * 2 + 1];
                acc[0] += pn * xv0.x; acc[1] += pn * xv0.y;
                acc[2] += pn * xv0.z; acc[3] += pn * xv0.w;
                acc[4] += pn * xv1.x; acc[5] += pn * xv1.y;
                acc[6] += pn * xv1.z; acc[7] += pn * xv1.w;
            }
        }
    }
    float* dst = &g_part[b][seg][w][0];
    if (lane == 0) { dst[0] = mstate; dst[1] = lstate; }
#pragma unroll
    for (int j = 0; j < 8; j++) dst[2 + lane * 8 + j] = acc[j];
}

// ---------------- merge flash partials -> ctxA (with homogeneous col) --------
__global__ void k_merge() {
    int b = blockIdx.x, t = threadIdx.x;
#pragma unroll
    for (int h = 0; h < 8; h++) {
        float M = NEG_BIG;
#pragma unroll
        for (int s = 0; s < SEG; s++) M = fmaxf(M, g_part[b][s][h][0]);
        float L = 0.f, a = 0.f;
#pragma unroll
        for (int s = 0; s < SEG; s++) {
            float ms = g_part[b][s][h][0];
            float wg = (ms > 0.5f * NEG_BIG) ? expf(ms - M) : 0.f;
            L += wg * g_part[b][s][h][1];
            a += wg * g_part[b][s][h][2 + t];
        }
        g_ctxA[b][h * 256 + t] = a / L;
    }
    if (t == 0) g_ctxA[b][2048] = 1.f;
    for (int i = 2049 + t; i < K2; i += 256) g_ctxA[b][i] = 0.f;
}

// ---------------- GEMM2 (split-K): qpkpart = ctxA @ G ----------------
__global__ void __launch_bounds__(256) k_gemm2() {
    int n0 = blockIdx.x * 96, m0 = blockIdx.y * 32, s = blockIdx.z;
    int c0 = (s * 65) / 8, c1 = ((s + 1) * 65) / 8;
    int t = threadIdx.x, tx = t & 31, ty = t >> 5;
    __shared__ __align__(16) float As[32][33];
    __shared__ __align__(16) float Bs[32][96];
    float acc[4][3] = {};
    for (int c = c0; c < c1; c++) {
        int k0 = c * 32;
#pragma unroll
        for (int l = 0; l < 4; l++) {
            int idx = t + 256 * l;
            As[idx >> 5][idx & 31] = g_ctxA[m0 + (idx >> 5)][k0 + (idx & 31)];
        }
#pragma unroll
        for (int l = 0; l < 3; l++) {
            int idx = t + 256 * l;
            int r = idx / 24, cc = idx % 24;
            *(float4*)&Bs[r][cc * 4] = *(const float4*)&g_G[k0 + r][n0 + cc * 4];
        }
        __syncthreads();
#pragma unroll
        for (int kk = 0; kk < 32; kk++) {
            float a0 = As[ty * 4 + 0][kk], a1 = As[ty * 4 + 1][kk];
            float a2 = As[ty * 4 + 2][kk], a3 = As[ty * 4 + 3][kk];
            float b0 = Bs[kk][tx * 3 + 0], b1 = Bs[kk][tx * 3 + 1], b2 = Bs[kk][tx * 3 + 2];
            acc[0][0] += a0 * b0; acc[0][1] += a0 * b1; acc[0][2] += a0 * b2;
            acc[1][0] += a1 * b0; acc[1][1] += a1 * b1; acc[1][2] += a1 * b2;
            acc[2][0] += a2 * b0; acc[2][1] += a2 * b1; acc[2][2] += a2 * b2;
            acc[3][0] += a3 * b0; acc[3][1] += a3 * b1; acc[3][2] += a3 * b2;
        }
        __syncthreads();
    }
#pragma unroll
    for (int i = 0; i < 4; i++)
#pragma unroll
        for (int j = 0; j < 3; j++)
            g_qpkpart[s][m0 + ty * 4 + i][n0 + tx * 3 + j] = acc[i][j];
}

// ---------------- K4: pointer logits (with split-K reduce prologue) ----------
__global__ void k_point(const float* __restrict__ x) {
    int seg = blockIdx.x, b = blockIdx.y;
    int t = threadIdx.x, lane = t & 31, w = t >> 5;
    __shared__ float qs[Ec];
    __shared__ float s_ub;
    {
        float a = 0.f;
#pragma unroll
        for (int s = 0; s < 8; s++) a += g_qpkpart[s][b][t];
        qs[t] = a;
        if (t == 0) {
            float u = 0.f;
#pragma unroll
            for (int s = 0; s < 8; s++) u += g_qpkpart[s][b][256];
            s_ub = u;
        }
    }
    __syncthreads();
    float ub = s_ub;
    float q0[8];
#pragma unroll
    for (int j = 0; j < 8; j++) q0[j] = qs[lane * 8 + j];
    int nbase = seg * 256 + w * 32;
    for (int i = 0; i < 32; i++) {
        int n = nbase + i;
        const float4* xr = (const float4*)(x + ((size_t)b * Nc + n) * Ec);
        float4 a0 = xr[lane * 2], a1 = xr[lane * 2 + 1];
        float s = q0[0] * a0.x + q0[1] * a0.y + q0[2] * a0.z + q0[3] * a0.w
                + q0[4] * a1.x + q0[5] * a1.y + q0[6] * a1.z + q0[7] * a1.w;
#pragma unroll
        for (int off = 16; off; off >>= 1) s += __shfl_xor_sync(0xffffffffu, s, off);
        if (lane == 0) {
            g_u[b][n] = g_mask[b][n] ? NEG_BIG : CLIPC * tanhf(s + ub);
        }
    }
}

// ---------------- K5: softmax + argmax + state update + outputs --------------
__global__ void k_select(const float* __restrict__ x, const float* __restrict__ demand,
                         float* __restrict__ out, int t_step, int write_route) {
    int b = blockIdx.x, t = threadIdx.x;  // 1024 threads
    __shared__ float sval[32];
    __shared__ int sidx[32];
    __shared__ float ssum[32];
    __shared__ int s_node;
    __shared__ float s_max;

    float v = g_u[b][t];
    int idx = t;
#pragma unroll
    for (int off = 16; off; off >>= 1) {
        float ov = __shfl_xor_sync(0xffffffffu, v, off);
        int oi = __shfl_xor_sync(0xffffffffu, idx, off);
        if (ov > v || (ov == v && oi < idx)) { v = ov; idx = oi; }
    }
    if ((t & 31) == 0) { sval[t >> 5] = v; sidx[t >> 5] = idx; }
    __syncthreads();
    if (t < 32) {
        v = sval[t]; idx = sidx[t];
#pragma unroll
        for (int off = 16; off; off >>= 1) {
            float ov = __shfl_xor_sync(0xffffffffu, v, off);
            int oi = __shfl_xor_sync(0xffffffffu, idx, off);
            if (ov > v || (ov == v && oi < idx)) { v = ov; idx = oi; }
        }
        if (t == 0) { s_node = idx; s_max = v; }
    }
    __syncthreads();
    float mx = s_max;
    int node = s_node;
    float u = g_u[b][t];
    float p = expf(u - mx);

    float s = p;
#pragma unroll
    for (int off = 16; off; off >>= 1) s += __shfl_xor_sync(0xffffffffu, s, off);
    if ((t & 31) == 0) ssum[t >> 5] = s;
    __syncthreads();
    if (t < 32) {
        s = ssum[t];
#pragma unroll
        for (int off = 16; off; off >>= 1) s += __shfl_xor_sync(0xffffffffu, s, off);
        if (t == 0) ssum[0] = s;
    }
    __syncthreads();
    out[(size_t)t_step * Bc * Nc + (size_t)b * Nc + t] = p / ssum[0];

    if (t == 0 && write_route)
        out[(size_t)Tc * Bc * Nc + (size_t)t_step * Bc + b] = (float)node;
    if (t == 0) {
        g_cap[b] = g_cap[b] - demand[(size_t)b * Nc + node];
        g_cur[b] = node;
    }
    if (t < Ec) {
        if (node != 0 && g_visited[b][node] == 0)
            g_sumx[b][t] -= x[((size_t)b * Nc + node) * Ec + t];
    }
    __syncthreads();
    if (t == 0) {
        if (node != 0 && g_visited[b][node] == 0) {
            g_visited[b][node] = 1;
            g_cnt[b] -= 1.f;
        }
    }
}

// ---------------- launch ----------------
extern "C" void kernel_launch(void* const* d_in, const int* in_sizes, int n_in,
                              void* d_out, int out_size) {
    const float* x      = (const float*)d_in[0];
    const float* demand = (const float*)d_in[1];
    const float* cap0   = (const float*)d_in[2];
    const float* Wc     = (const float*)d_in[3];
    const float* bc     = (const float*)d_in[4];
    const float* Wqkv   = (const float*)d_in[5];
    const float* bqkv   = (const float*)d_in[6];
    const float* Wo     = (const float*)d_in[7];
    const float* bo     = (const float*)d_in[8];
    const float* Wpq    = (const float*)d_in[9];
    const float* bpq    = (const float*)d_in[10];
    const float* Wpk    = (const float*)d_in[11];
    const float* bpk    = (const float*)d_in[12];
    float* out = (float*)d_out;
    int write_route = (out_size > Tc * Bc * Nc) ? 1 : 0;

    k_init<<<Bc, 256>>>(x, cap0);
    // fold weights (once per launch)
    pZero<<<2048, 256>>>();
    pA1<<<514, 256>>>(Wc, bc, Wqkv, bqkv);
    pWkT<<<256, 256>>>(Wqkv);
    pWbig<<<514, 256>>>(bqkv);
    pT2<<<257, 256>>>(Wo, bo, Wpq, bpq);
    pWpkT<<<256, 256>>>(Wpk);
    pT3<<<257, 288>>>(bpk);
    pG<<<2049, 288>>>(Wqkv, bqkv);

    for (int t = 0; t < Tc; t++) {
        k_state<<<Bc, 256>>>(x, demand);
        k_gemm1<<<dim3(17, 8), 256>>>();
        k_attn<<<dim3(SEG, Bc), 256>>>(x);
        k_merge<<<Bc, 256>>>();
        k_gemm2<<<dim3(3, 8, 8), 256>>>();
        k_point<<<dim3(SEG, Bc), 256>>>(x);
        k_select<<<Bc, 1024>>>(x, demand, out, t, write_route);
    }
}

// round 5
// speedup vs baseline: 1.8514x; 1.3486x over previous
#include <cuda_runtime.h>
#include <math.h>

#define Bc 256
#define Nc 1024
#define Ec 256
#define Hc 8
#define Tc 64
#define SEG 8
#define NSEG 128        // N / SEG
#define SUBN 32
#define XPITCH 260      // padded row pitch (floats) for staged x
#define NEG_BIG (-1e30f)
#define CLIPC 10.0f

#define K1 544
#define N1 2176
#define K2 2080
#define N2 288

// ---------------- f32x2 packed helpers (Blackwell) ----------------
__device__ __forceinline__ unsigned long long pk2(float lo, float hi) {
    unsigned long long r;
    asm("mov.b64 %0, {%1, %2};" : "=l"(r) : "f"(lo), "f"(hi));
    return r;
}
__device__ __forceinline__ void upk2(unsigned long long v, float& lo, float& hi) {
    asm("mov.b64 {%0, %1}, %2;" : "=f"(lo), "=f"(hi) : "l"(v));
}
__device__ __forceinline__ void fma2(unsigned long long& d, unsigned long long a, unsigned long long b) {
    asm("fma.rn.f32x2 %0, %1, %2, %0;" : "+l"(d) : "l"(a), "l"(b));
}
__device__ __forceinline__ unsigned long long mul2(unsigned long long a, unsigned long long b) {
    unsigned long long r;
    asm("mul.rn.f32x2 %0, %1, %2;" : "=l"(r) : "l"(a), "l"(b));
    return r;
}

// ---------------- persistent device state ----------------
__device__ float g_sumx[Bc][Ec];
__device__ float g_cnt[Bc];
__device__ float g_cap[Bc];
__device__ int   g_cur[Bc];
__device__ unsigned char g_visited[Bc][Nc];
__device__ unsigned char g_mask[Bc][Nc];
__device__ float g_part[Bc][SEG][Hc][Ec + 2];

__device__ float g_A1[514][256];
__device__ float g_WkT[256][256];
__device__ float g_Wbig[K1][N1];
__device__ float g_cat[Bc][K1];
__device__ float g_qkflat[Bc][N1];
__device__ float g_T2ext[257][256];
__device__ float g_WpkT[256][256];
__device__ float g_T3ext[257][288];
__device__ float g_G[K2][N2];
__device__ float g_ctxA[Bc][K2];
__device__ float g_qpkpart[8][Bc][N2];

// ---------------- init ----------------
__global__ void k_init(const float* __restrict__ x, const float* __restrict__ cap0) {
    int b = blockIdx.x, t = threadIdx.x;
    const float* xb = x + (size_t)b * Nc * Ec;
    float s = 0.f;
    for (int n = 0; n < Nc; n++) s += xb[(size_t)n * Ec + t];
    g_sumx[b][t] = s;
    for (int i = t; i < Nc; i += 256) g_visited[b][i] = 0;
    if (t == 0) {
        g_cnt[b] = (float)Nc;
        g_cap[b] = cap0[b];
        g_cur[b] = 0;
    }
}

// ---------------- precompute (once per launch) ----------------
__global__ void pZero() {
    int idx = blockIdx.x * 256 + threadIdx.x;
    float* w = &g_Wbig[0][0];
    for (int i = idx; i < K1 * N1; i += gridDim.x * 256) w[i] = 0.f;
    float* g = &g_G[0][0];
    for (int i = idx; i < K2 * N2; i += gridDim.x * 256) g[i] = 0.f;
}

__global__ void pA1(const float* __restrict__ Wc, const float* __restrict__ bc,
                    const float* __restrict__ Wqkv, const float* __restrict__ bqkv) {
    int i = blockIdx.x, t = threadIdx.x;
    __shared__ float wrow[256];
    wrow[t] = (i < 513) ? Wc[i * 256 + t] : bc[t];
    __syncthreads();
    float s = (i == 513) ? bqkv[t] : 0.f;
    for (int e = 0; e < 256; e++) s += wrow[e] * Wqkv[e * 768 + t];
    g_A1[i][t] = s;
}

__global__ void pWkT(const float* __restrict__ Wqkv) {
    int d = blockIdx.x, e = threadIdx.x;
    g_WkT[d][e] = Wqkv[e * 768 + 256 + d];
}

__global__ void pWbig(const float* __restrict__ bqkv) {
    int i = blockIdx.x, e = threadIdx.x;
    __shared__ float a1[256];
    a1[e] = g_A1[i][e];
    __syncthreads();
    const float scale = 0.17677669529663687f;
#pragma unroll
    for (int h = 0; h < 8; h++) {
        float s = 0.f;
#pragma unroll
        for (int dd = 0; dd < 32; dd++) s += a1[h * 32 + dd] * g_WkT[h * 32 + dd][e];
        g_Wbig[i][h * 256 + e] = scale * s;
    }
    if (e < 8) {
        float s = 0.f;
        for (int dd = 0; dd < 32; dd++) s += a1[e * 32 + dd] * bqkv[256 + e * 32 + dd];
        g_Wbig[i][2048 + e] = scale * s;
    }
}

__global__ void pT2(const float* __restrict__ Wo, const float* __restrict__ bo,
                    const float* __restrict__ Wpq, const float* __restrict__ bpq) {
    int i = blockIdx.x, t = threadIdx.x;
    __shared__ float wrow[256];
    wrow[t] = (i < 256) ? Wo[i * 256 + t] : bo[t];
    __syncthreads();
    float s = (i == 256) ? bpq[t] : 0.f;
    for (int k = 0; k < 256; k++) s += wrow[k] * Wpq[k * 256 + t];
    g_T2ext[i][t] = s;
}

__global__ void pWpkT(const float* __restrict__ Wpk) {
    int j2 = blockIdx.x, d = threadIdx.x;
    g_WpkT[j2][d] = Wpk[d * 256 + j2];
}

__global__ void pT3(const float* __restrict__ bpk) {
    int j = blockIdx.x, t = threadIdx.x;
    __shared__ float t2[256];
    if (t < 256) t2[t] = g_T2ext[j][t];
    __syncthreads();
    if (t < 256) {
        float s = 0.f;
        for (int k = 0; k < 256; k++) s += t2[k] * g_WpkT[k][t];
        g_T3ext[j][t] = s;
    } else if (t == 256) {
        float s = 0.f;
        for (int k = 0; k < 256; k++) s += t2[k] * bpk[k];
        g_T3ext[j][256] = s;
    }
}

__global__ void pG(const float* __restrict__ Wqkv, const float* __restrict__ bqkv) {
    int he = blockIdx.x, t = threadIdx.x;
    __shared__ float sw[256];
    if (he < 2048) {
        int h = he >> 8, e = he & 255;
        if (t < 32) sw[t] = Wqkv[e * 768 + 512 + h * 32 + t];
        __syncthreads();
        if (t < 257) {
            float s = 0.f;
            int jb = h * 32;
#pragma unroll
            for (int jl = 0; jl < 32; jl++) s += sw[jl] * g_T3ext[jb + jl][t];
            g_G[he][t] = s;
        }
    } else {
        if (t < 256) sw[t] = bqkv[512 + t];
        __syncthreads();
        if (t < 257) {
            float s = g_T3ext[256][t];
            for (int j = 0; j < 256; j++) s += sw[j] * g_T3ext[j][t];
            g_G[2048][t] = s;
        }
    }
}

// ---------------- per-step: mask + cat build ----------------
__global__ void k_state(const float* __restrict__ x, const float* __restrict__ demand) {
    int b = blockIdx.x, t = threadIdx.x;
    __shared__ int red[8];
    float cap = g_cap[b];
    int cur = g_cur[b];
    float cnt = g_cnt[b];
    g_cat[b][t] = g_sumx[b][t] / cnt;
    g_cat[b][256 + t] = x[((size_t)b * Nc + cur) * Ec + t];
    if (t == 0) { g_cat[b][512] = cap; g_cat[b][513] = 1.f; }
    if (t < 30) g_cat[b][514 + t] = 0.f;
    int allm = 1;
    for (int n = t; n < Nc; n += 256) {
        int m = (g_visited[b][n] != 0) || (demand[(size_t)b * Nc + n] > cap);
        if (n == 0) m = (cur == 0) ? 1 : m;
        g_mask[b][n] = (unsigned char)m;
        allm &= m;
    }
    allm = __all_sync(0xffffffffu, allm);
    if ((t & 31) == 0) red[t >> 5] = allm;
    __syncthreads();
    if (t == 0) {
        int a = 1;
        for (int w = 0; w < 8; w++) a &= red[w];
        if (a) g_mask[b][0] = 0;
    }
}

// ---------------- GEMM1: qkflat = cat @ Wbig (f32x2) ----------------
__global__ void __launch_bounds__(256) k_gemm1() {
    int n0 = blockIdx.x * 128, m0 = blockIdx.y * 32;
    int t = threadIdx.x, tx = t & 31, ty = t >> 5;
    __shared__ __align__(16) float As[32][33];
    __shared__ __align__(16) float Bs[32][128];
    unsigned long long acc2[4][2];
#pragma unroll
    for (int i = 0; i < 4; i++) { acc2[i][0] = 0ull; acc2[i][1] = 0ull; }
    for (int k0 = 0; k0 < K1; k0 += 32) {
#pragma unroll
        for (int l = 0; l < 4; l++) {
            int idx = t + 256 * l;
            As[idx >> 5][idx & 31] = g_cat[m0 + (idx >> 5)][k0 + (idx & 31)];
        }
#pragma unroll
        for (int l = 0; l < 4; l++) {
            int idx = t + 256 * l;
            int r = idx >> 5, c = idx & 31;
            *(float4*)&Bs[r][c * 4] = *(const float4*)&g_Wbig[k0 + r][n0 + c * 4];
        }
        __syncthreads();
#pragma unroll
        for (int kk = 0; kk < 32; kk++) {
            ulonglong2 bv = *(const ulonglong2*)&Bs[kk][tx * 4];
#pragma unroll
            for (int i = 0; i < 4; i++) {
                float a = As[ty * 4 + i][kk];
                unsigned long long ad = pk2(a, a);
                fma2(acc2[i][0], ad, bv.x);
                fma2(acc2[i][1], ad, bv.y);
            }
        }
        __syncthreads();
    }
#pragma unroll
    for (int i = 0; i < 4; i++) {
        float4 v;
        upk2(acc2[i][0], v.x, v.y);
        upk2(acc2[i][1], v.z, v.w);
        *(float4*)&g_qkflat[m0 + ty * 4 + i][n0 + tx * 4] = v;
    }
}

// ---------------- K2: fused flash attention over x ----------------
// grid (SEG=8, Bc). 256 thr. Score phase: warp w -> rows w*4..w*4+3 (all heads,
// qk in regs, shfl reduce). Softmax: warp w owns head w m/l. Acc phase: warp
// dims-sliced: warps (w&3) own 64 dims, warp-half (w>>2) owns 16 of 32 rows;
// x smem read ONCE per chunk in acc.
__global__ void __launch_bounds__(256, 2)
k_attn(const float* __restrict__ x) {
    int seg = blockIdx.x, b = blockIdx.y;
    int t = threadIdx.x, lane = t & 31, w = t >> 5;
    __shared__ __align__(16) float xs[SUBN * XPITCH];   // ~33.3 KB
    __shared__ __align__(16) float ss[SUBN][12];        // scores -> p, padded
    __shared__ float alpha_s[8];

    // qk for all heads, this lane's 8 dims, packed as f32x2
    unsigned long long qkr2[8][4];
#pragma unroll
    for (int h = 0; h < 8; h++) {
        float4 q0 = *(const float4*)&g_qkflat[b][h * 256 + lane * 8];
        float4 q1 = *(const float4*)&g_qkflat[b][h * 256 + lane * 8 + 4];
        qkr2[h][0] = pk2(q0.x, q0.y); qkr2[h][1] = pk2(q0.z, q0.w);
        qkr2[h][2] = pk2(q1.x, q1.y); qkr2[h][3] = pk2(q1.z, q1.w);
    }
    float sb[8];
#pragma unroll
    for (int h = 0; h < 8; h++) sb[h] = g_qkflat[b][2048 + h];

    int dimbase = (w & 3) * 64;       // acc-phase dim slice
    int nq0 = (w >> 2) * 16;          // acc-phase row half
    unsigned long long acc2[8];
#pragma unroll
    for (int h = 0; h < 8; h++) acc2[h] = 0ull;
    float mstate = NEG_BIG, lstate = 0.f;

    int n0 = seg * NSEG;
    for (int c = 0; c < NSEG / SUBN; c++) {
        int nb = n0 + c * SUBN;
        __syncthreads();
        {   // stage 32 rows with padded pitch
            const float4* src = (const float4*)(x + ((size_t)b * Nc + nb) * Ec);
#pragma unroll
            for (int i = 0; i < 8; i++) {
                int g = t + 256 * i;
                int row = g >> 6, c4 = g & 63;
                *(float4*)&xs[row * XPITCH + c4 * 4] = src[row * 64 + c4];
            }
        }
        __syncthreads();

        // ---- scores ----
#pragma unroll
        for (int i = 0; i < 4; i++) {
            int nl = w * 4 + i;
            float4 xv0 = *(const float4*)&xs[nl * XPITCH + lane * 8];
            float4 xv1 = *(const float4*)&xs[nl * XPITCH + lane * 8 + 4];
            unsigned long long x2[4] = {pk2(xv0.x, xv0.y), pk2(xv0.z, xv0.w),
                                        pk2(xv1.x, xv1.y), pk2(xv1.z, xv1.w)};
            float s[8];
#pragma unroll
            for (int h = 0; h < 8; h++) {
                unsigned long long s2 = 0ull;
#pragma unroll
                for (int j = 0; j < 4; j++) fma2(s2, qkr2[h][j], x2[j]);
                float lo, hi;
                upk2(s2, lo, hi);
                s[h] = lo + hi;
            }
#pragma unroll
            for (int off = 16; off; off >>= 1)
#pragma unroll
                for (int h = 0; h < 8; h++)
                    s[h] += __shfl_xor_sync(0xffffffffu, s[h], off);
            if (lane < 8) {
                int gm = g_mask[b][nb + nl];
                float val;
#pragma unroll
                for (int h = 0; h < 8; h++) if (lane == h) val = s[h] + sb[h];
                ss[nl][lane] = gm ? NEG_BIG : val;
            }
        }
        __syncthreads();

        // ---- online softmax: warp w owns head w ----
        {
            float v = ss[lane][w];
            float mx = v;
#pragma unroll
            for (int off = 16; off; off >>= 1)
                mx = fmaxf(mx, __shfl_xor_sync(0xffffffffu, mx, off));
            float mnew = fmaxf(mstate, mx);
            float alpha = (mstate > 0.5f * NEG_BIG) ? expf(mstate - mnew) : 0.f;
            float p = (v > 0.5f * NEG_BIG) ? expf(v - mnew) : 0.f;
            ss[lane][w] = p;
            float ps = p;
#pragma unroll
            for (int off = 16; off; off >>= 1)
                ps += __shfl_xor_sync(0xffffffffu, ps, off);
            lstate = lstate * alpha + ps;
            mstate = mnew;
            if (lane == 0) alpha_s[w] = alpha;
        }
        __syncthreads();

        // ---- acc: dims-sliced, x read once ----
        {
            unsigned long long ad[8];
#pragma unroll
            for (int h = 0; h < 8; h++) {
                float a = alpha_s[h];
                ad[h] = pk2(a, a);
            }
#pragma unroll
            for (int h = 0; h < 8; h++) acc2[h] = mul2(acc2[h], ad[h]);
            for (int r = 0; r < 16; r++) {
                int n = nq0 + r;
                float2 xv = *(const float2*)&xs[n * XPITCH + dimbase + lane * 2];
                unsigned long long xp = pk2(xv.x, xv.y);
                float4 pa = *(const float4*)&ss[n][0];
                float4 pb = *(const float4*)&ss[n][4];
                fma2(acc2[0], pk2(pa.x, pa.x), xp);
                fma2(acc2[1], pk2(pa.y, pa.y), xp);
                fma2(acc2[2], pk2(pa.z, pa.z), xp);
                fma2(acc2[3], pk2(pa.w, pa.w), xp);
                fma2(acc2[4], pk2(pb.x, pb.x), xp);
                fma2(acc2[5], pk2(pb.y, pb.y), xp);
                fma2(acc2[6], pk2(pb.z, pb.z), xp);
                fma2(acc2[7], pk2(pb.w, pb.w), xp);
            }
        }
    }

    // m/l for head w
    if (lane == 0) {
        g_part[b][seg][w][0] = mstate;
        g_part[b][seg][w][1] = lstate;
    }

    // combine the two row-halves per (head, dim) via smem, write partials
    __syncthreads();
    float* buf = xs;  // reuse (8 KB needed)
    if (w >= 4) {
        int ds = w & 3;
#pragma unroll
        for (int h = 0; h < 8; h++) {
            float lo, hi;
            upk2(acc2[h], lo, hi);
            buf[(ds * 8 + h) * 64 + lane * 2] = lo;
            buf[(ds * 8 + h) * 64 + lane * 2 + 1] = hi;
        }
    }
    __syncthreads();
    if (w < 4) {
        int ds = w;
#pragma unroll
        for (int h = 0; h < 8; h++) {
            float lo, hi;
            upk2(acc2[h], lo, hi);
            lo += buf[(ds * 8 + h) * 64 + lane * 2];
            hi += buf[(ds * 8 + h) * 64 + lane * 2 + 1];
            g_part[b][seg][h][2 + ds * 64 + lane * 2] = lo;
            g_part[b][seg][h][2 + ds * 64 + lane * 2 + 1] = hi;
        }
    }
}

// ---------------- merge flash partials -> ctxA ----------------
__global__ void k_merge() {
    int b = blockIdx.x, t = threadIdx.x;
#pragma unroll
    for (int h = 0; h < 8; h++) {
        float M = NEG_BIG;
#pragma unroll
        for (int s = 0; s < SEG; s++) M = fmaxf(M, g_part[b][s][h][0]);
        float L = 0.f, a = 0.f;
#pragma unroll
        for (int s = 0; s < SEG; s++) {
            float ms = g_part[b][s][h][0];
            float wg = (ms > 0.5f * NEG_BIG) ? expf(ms - M) : 0.f;
            L += wg * g_part[b][s][h][1];
            a += wg * g_part[b][s][h][2 + t];
        }
        g_ctxA[b][h * 256 + t] = a / L;
    }
    if (t == 0) g_ctxA[b][2048] = 1.f;
    for (int i = 2049 + t; i < K2; i += 256) g_ctxA[b][i] = 0.f;
}

// ---------------- GEMM2 (split-K) ----------------
__global__ void __launch_bounds__(256) k_gemm2() {
    int n0 = blockIdx.x * 96, m0 = blockIdx.y * 32, s = blockIdx.z;
    int c0 = (s * 65) / 8, c1 = ((s + 1) * 65) / 8;
    int t = threadIdx.x, tx = t & 31, ty = t >> 5;
    __shared__ __align__(16) float As[32][33];
    __shared__ __align__(16) float Bs[32][96];
    float acc[4][3] = {};
    for (int c = c0; c < c1; c++) {
        int k0 = c * 32;
#pragma unroll
        for (int l = 0; l < 4; l++) {
            int idx = t + 256 * l;
            As[idx >> 5][idx & 31] = g_ctxA[m0 + (idx >> 5)][k0 + (idx & 31)];
        }
#pragma unroll
        for (int l = 0; l < 3; l++) {
            int idx = t + 256 * l;
            int r = idx / 24, cc = idx % 24;
            *(float4*)&Bs[r][cc * 4] = *(const float4*)&g_G[k0 + r][n0 + cc * 4];
        }
        __syncthreads();
#pragma unroll
        for (int kk = 0; kk < 32; kk++) {
            float a0 = As[ty * 4 + 0][kk], a1 = As[ty * 4 + 1][kk];
            float a2 = As[ty * 4 + 2][kk], a3 = As[ty * 4 + 3][kk];
            float b0 = Bs[kk][tx * 3 + 0], b1 = Bs[kk][tx * 3 + 1], b2 = Bs[kk][tx * 3 + 2];
            acc[0][0] += a0 * b0; acc[0][1] += a0 * b1; acc[0][2] += a0 * b2;
            acc[1][0] += a1 * b0; acc[1][1] += a1 * b1; acc[1][2] += a1 * b2;
            acc[2][0] += a2 * b0; acc[2][1] += a2 * b1; acc[2][2] += a2 * b2;
            acc[3][0] += a3 * b0; acc[3][1] += a3 * b1; acc[3][2] += a3 * b2;
        }
        __syncthreads();
    }
#pragma unroll
    for (int i = 0; i < 4; i++)
#pragma unroll
        for (int j = 0; j < 3; j++)
            g_qpkpart[s][m0 + ty * 4 + i][n0 + tx * 3 + j] = acc[i][j];
}

// ---------------- fused pointer logits + softmax + argmax + update ----------
__global__ void __launch_bounds__(256) k_pointsel(
    const float* __restrict__ x, const float* __restrict__ demand,
    float* __restrict__ out, int t_step, int write_route) {
    int b = blockIdx.x;
    int t = threadIdx.x, lane = t & 31, w = t >> 5;
    __shared__ float qs[Ec];
    __shared__ float u_s[Nc];
    __shared__ float s_ub;
    __shared__ float rv[8];
    __shared__ int ri[8];
    __shared__ float rs[8];
    __shared__ int s_node;
    __shared__ float s_max, s_sum;

    {   // split-K reduce of qpk
        float a = 0.f;
#pragma unroll
        for (int s = 0; s < 8; s++) a += g_qpkpart[s][b][t];
        qs[t] = a;
        if (t == 0) {
            float u = 0.f;
#pragma unroll
            for (int s = 0; s < 8; s++) u += g_qpkpart[s][b][256];
            s_ub = u;
        }
    }
    __syncthreads();
    float ub = s_ub;
    float q0[8];
#pragma unroll
    for (int j = 0; j < 8; j++) q0[j] = qs[lane * 8 + j];

    // phase A: logits for 128 rows per warp
    int rbase = w * 128;
    for (int i = 0; i < 128; i += 2) {
        int n0 = rbase + i, n1 = n0 + 1;
        const float4* xr0 = (const float4*)(x + ((size_t)b * Nc + n0) * Ec);
        const float4* xr1 = (const float4*)(x + ((size_t)b * Nc + n1) * Ec);
        float4 a0 = xr0[lane * 2], a1 = xr0[lane * 2 + 1];
        float4 c0 = xr1[lane * 2], c1 = xr1[lane * 2 + 1];
        float s0 = q0[0] * a0.x + q0[1] * a0.y + q0[2] * a0.z + q0[3] * a0.w
                 + q0[4] * a1.x + q0[5] * a1.y + q0[6] * a1.z + q0[7] * a1.w;
        float s1 = q0[0] * c0.x + q0[1] * c0.y + q0[2] * c0.z + q0[3] * c0.w
                 + q0[4] * c1.x + q0[5] * c1.y + q0[6] * c1.z + q0[7] * c1.w;
#pragma unroll
        for (int off = 16; off; off >>= 1) {
            s0 += __shfl_xor_sync(0xffffffffu, s0, off);
            s1 += __shfl_xor_sync(0xffffffffu, s1, off);
        }
        if (lane == 0) {
            u_s[n0] = g_mask[b][n0] ? NEG_BIG : CLIPC * tanhf(s0 + ub);
            u_s[n1] = g_mask[b][n1] ? NEG_BIG : CLIPC * tanhf(s1 + ub);
        }
    }
    __syncthreads();

    // phase B: argmax (first-occurrence tie), softmax, write, update
    float uv[4];
    float bv = -3.4e38f; int bi = 0x7fffffff;
#pragma unroll
    for (int k = 0; k < 4; k++) {
        int n = t + 256 * k;
        uv[k] = u_s[n];
        if (uv[k] > bv || (uv[k] == bv && n < bi)) { bv = uv[k]; bi = n; }
    }
#pragma unroll
    for (int off = 16; off; off >>= 1) {
        float ov = __shfl_xor_sync(0xffffffffu, bv, off);
        int oi = __shfl_xor_sync(0xffffffffu, bi, off);
        if (ov > bv || (ov == bv && oi < bi)) { bv = ov; bi = oi; }
    }
    if (lane == 0) { rv[w] = bv; ri[w] = bi; }
    __syncthreads();
    if (t == 0) {
        float mv = rv[0]; int mi = ri[0];
#pragma unroll
        for (int k = 1; k < 8; k++)
            if (rv[k] > mv || (rv[k] == mv && ri[k] < mi)) { mv = rv[k]; mi = ri[k]; }
        s_max = mv; s_node = mi;
    }
    __syncthreads();
    float mx = s_max;
    int node = s_node;

    float pk[4];
    float psum = 0.f;
#pragma unroll
    for (int k = 0; k < 4; k++) { pk[k] = expf(uv[k] - mx); psum += pk[k]; }
#pragma unroll
    for (int off = 16; off; off >>= 1) psum += __shfl_xor_sync(0xffffffffu, psum, off);
    if (lane == 0) rs[w] = psum;
    __syncthreads();
    if (t == 0) {
        float s = 0.f;
#pragma unroll
        for (int k = 0; k < 8; k++) s += rs[k];
        s_sum = s;
    }
    __syncthreads();
    float inv = 1.f / s_sum;
    size_t ob = (size_t)t_step * Bc * Nc + (size_t)b * Nc;
#pragma unroll
    for (int k = 0; k < 4; k++) out[ob + t + 256 * k] = pk[k] * inv;

    if (t == 0 && write_route)
        out[(size_t)Tc * Bc * Nc + (size_t)t_step * Bc + b] = (float)node;
    if (t == 0) {
        g_cap[b] = g_cap[b] - demand[(size_t)b * Nc + node];
        g_cur[b] = node;
    }
    // t covers dims 0..255
    if (node != 0 && g_visited[b][node] == 0)
        g_sumx[b][t] -= x[((size_t)b * Nc + node) * Ec + t];
    __syncthreads();
    if (t == 0) {
        if (node != 0 && g_visited[b][node] == 0) {
            g_visited[b][node] = 1;
            g_cnt[b] -= 1.f;
        }
    }
}

// ---------------- launch ----------------
extern "C" void kernel_launch(void* const* d_in, const int* in_sizes, int n_in,
                              void* d_out, int out_size) {
    const float* x      = (const float*)d_in[0];
    const float* demand = (const float*)d_in[1];
    const float* cap0   = (const float*)d_in[2];
    const float* Wc     = (const float*)d_in[3];
    const float* bc     = (const float*)d_in[4];
    const float* Wqkv   = (const float*)d_in[5];
    const float* bqkv   = (const float*)d_in[6];
    const float* Wo     = (const float*)d_in[7];
    const float* bo     = (const float*)d_in[8];
    const float* Wpq    = (const float*)d_in[9];
    const float* bpq    = (const float*)d_in[10];
    const float* Wpk    = (const float*)d_in[11];
    const float* bpk    = (const float*)d_in[12];
    float* out = (float*)d_out;
    int write_route = (out_size > Tc * Bc * Nc) ? 1 : 0;

    k_init<<<Bc, 256>>>(x, cap0);
    pZero<<<2048, 256>>>();
    pA1<<<514, 256>>>(Wc, bc, Wqkv, bqkv);
    pWkT<<<256, 256>>>(Wqkv);
    pWbig<<<514, 256>>>(bqkv);
    pT2<<<257, 256>>>(Wo, bo, Wpq, bpq);
    pWpkT<<<256, 256>>>(Wpk);
    pT3<<<257, 288>>>(bpk);
    pG<<<2049, 288>>>(Wqkv, bqkv);

    for (int t = 0; t < Tc; t++) {
        k_state<<<Bc, 256>>>(x, demand);
        k_gemm1<<<dim3(17, 8), 256>>>();
        k_attn<<<dim3(SEG, Bc), 256>>>(x);
        k_merge<<<Bc, 256>>>();
        k_gemm2<<<dim3(3, 8, 8), 256>>>();
        k_pointsel<<<Bc, 256>>>(x, demand, out, t, write_route);
    }
}

// round 6
// speedup vs baseline: 2.1177x; 1.1438x over previous
#include <cuda_runtime.h>
#include <math.h>

#define Bc 256
#define Nc 1024
#define Ec 256
#define Hc 8
#define Tc 64
#define SEG 8
#define NSEG 128
#define SUBN 32
#define XPITCH 260
#define NEG_BIG (-1e30f)
#define CLIPC 10.0f

#define K1 544
#define N1 2176
#define K2 2080
#define N2 288

typedef unsigned long long ull;

// ---------------- f32x2 packed helpers ----------------
__device__ __forceinline__ ull pk2(float lo, float hi) {
    ull r; asm("mov.b64 %0, {%1, %2};" : "=l"(r) : "f"(lo), "f"(hi)); return r;
}
__device__ __forceinline__ void upk2(ull v, float& lo, float& hi) {
    asm("mov.b64 {%0, %1}, %2;" : "=f"(lo), "=f"(hi) : "l"(v));
}
__device__ __forceinline__ void fma2(ull& d, ull a, ull b) {
    asm("fma.rn.f32x2 %0, %1, %2, %0;" : "+l"(d) : "l"(a), "l"(b));
}
__device__ __forceinline__ ull mul2(ull a, ull b) {
    ull r; asm("mul.rn.f32x2 %0, %1, %2;" : "=l"(r) : "l"(a), "l"(b)); return r;
}

// 8-value cross-warp sum reduction with redistribution: 16 shfl.
// On return, lane 4*k (k=0..7) holds the full sum of value k.
__device__ __forceinline__ float red8(float s[8], int lane) {
#pragma unroll
    for (int j = 0; j < 8; j++) s[j] += __shfl_xor_sync(0xffffffffu, s[j], 16);
    float k4[4];
    int hi16 = lane & 16;
#pragma unroll
    for (int j = 0; j < 4; j++) k4[j] = hi16 ? s[j + 4] : s[j];
#pragma unroll
    for (int j = 0; j < 4; j++) k4[j] += __shfl_xor_sync(0xffffffffu, k4[j], 8);
    float c0 = (lane & 8) ? k4[2] : k4[0];
    float c1 = (lane & 8) ? k4[3] : k4[1];
    c0 += __shfl_xor_sync(0xffffffffu, c0, 4);
    c1 += __shfl_xor_sync(0xffffffffu, c1, 4);
    float v = (lane & 4) ? c1 : c0;
    v += __shfl_xor_sync(0xffffffffu, v, 2);
    v += __shfl_xor_sync(0xffffffffu, v, 1);
    return v;
}

// ---------------- persistent device state ----------------
__device__ float g_sumx[Bc][Ec];
__device__ float g_cnt[Bc];
__device__ float g_cap[Bc];
__device__ int   g_cur[Bc];
__device__ unsigned char g_visited[Bc][Nc];
__device__ unsigned char g_mask[Bc][Nc];
__device__ float g_part[Bc][SEG][Hc][Ec + 2];
__device__ int   g_syncnt[Bc];

__device__ float g_A1[514][256];
__device__ float g_WkT[256][256];
__device__ float g_Wbig[K1][N1];
__device__ float g_cat[Bc][K1];
__device__ float g_qkflat[Bc][N1];
__device__ float g_T2ext[257][256];
__device__ float g_WpkT[256][256];
__device__ float g_T3ext[257][288];
__device__ float g_G[K2][N2];
__device__ float g_ctxA[Bc][K2];
__device__ float g_qpkpart[8][Bc][N2];

// ======== P0a: init sums/visited + transposes + zero pads ========
__global__ void kP0a(const float* __restrict__ x, const float* __restrict__ cap0,
                     const float* __restrict__ Wqkv, const float* __restrict__ Wpk) {
    int blk = blockIdx.x, t = threadIdx.x;
    if (blk < 256) {                       // init per-b state
        int b = blk;
        const float* xb = x + (size_t)b * Nc * Ec;
        float s = 0.f;
        for (int n = 0; n < Nc; n++) s += xb[(size_t)n * Ec + t];
        g_sumx[b][t] = s;
        for (int i = t; i < Nc; i += 256) g_visited[b][i] = 0;
        if (t == 0) {
            g_cnt[b] = (float)Nc;
            g_cap[b] = cap0[b];
            g_cur[b] = 0;
            g_syncnt[b] = 0;
        }
    } else if (blk < 512) {                // WkT
        int d = blk - 256;
        g_WkT[d][t] = Wqkv[t * 768 + 256 + d];
    } else if (blk < 768) {                // WpkT
        int j2 = blk - 512;
        g_WpkT[j2][t] = Wpk[t * 256 + j2];
    } else {                               // zero Wbig, G, ctxA pads
        int idx = (blk - 768) * 256 + t;
        float* w = &g_Wbig[0][0];
        for (int i = idx; i < K1 * N1; i += 65536) w[i] = 0.f;
        float* g = &g_G[0][0];
        for (int i = idx; i < K2 * N2; i += 65536) g[i] = 0.f;
        for (int i = idx; i < Bc * 31; i += 65536) {
            int b = i / 31, j = i % 31;
            g_ctxA[b][2049 + j] = 0.f;
        }
    }
}

// ======== P0b: pA1 + pT2 + initial state/mask/cat ========
__global__ void kP0b(const float* __restrict__ x, const float* __restrict__ demand,
                     const float* __restrict__ cap0,
                     const float* __restrict__ Wc, const float* __restrict__ bc,
                     const float* __restrict__ Wqkv, const float* __restrict__ bqkv,
                     const float* __restrict__ Wo, const float* __restrict__ bo,
                     const float* __restrict__ Wpq, const float* __restrict__ bpq) {
    int blk = blockIdx.x, t = threadIdx.x;
    if (blk < 514) {                        // A1 = [Wc;bc] @ Wq (+bq)
        int i = blk;
        __shared__ float wrow[256];
        wrow[t] = (i < 513) ? Wc[i * 256 + t] : bc[t];
        __syncthreads();
        float s = (i == 513) ? bqkv[t] : 0.f;
        for (int e = 0; e < 256; e++) s += wrow[e] * Wqkv[e * 768 + t];
        g_A1[i][t] = s;
    } else if (blk < 771) {                 // T2 = [Wo;bo] @ Wpq (+bpq)
        int i = blk - 514;
        __shared__ float wrow[256];
        wrow[t] = (i < 256) ? Wo[i * 256 + t] : bo[t];
        __syncthreads();
        float s = (i == 256) ? bpq[t] : 0.f;
        for (int k = 0; k < 256; k++) s += wrow[k] * Wpq[k * 256 + t];
        g_T2ext[i][t] = s;
    } else {                                // state for step 0
        int b = blk - 771;
        __shared__ int red[8];
        float cap = cap0[b];
        g_cat[b][t] = g_sumx[b][t] / (float)Nc;
        g_cat[b][256 + t] = x[(size_t)b * Nc * Ec + t];
        if (t == 0) { g_cat[b][512] = cap; g_cat[b][513] = 1.f; }
        if (t < 30) g_cat[b][514 + t] = 0.f;
        int allm = 1;
        for (int n = t; n < Nc; n += 256) {
            int m = (demand[(size_t)b * Nc + n] > cap);
            if (n == 0) m = 1;  // at depot initially
            g_mask[b][n] = (unsigned char)m;
            allm &= m;
        }
        allm = __all_sync(0xffffffffu, allm);
        if ((t & 31) == 0) red[t >> 5] = allm;
        __syncthreads();
        if (t == 0) {
            int a = 1;
            for (int w = 0; w < 8; w++) a &= red[w];
            if (a) g_mask[b][0] = 0;
        }
    }
}

// ======== PW: pWbig + pT3 ========
__global__ void kPW(const float* __restrict__ bqkv, const float* __restrict__ bpk) {
    int blk = blockIdx.x, t = threadIdx.x;  // 288 threads
    if (blk < 514) {                        // Wbig rows
        int i = blk;
        __shared__ float a1[256];
        if (t < 256) a1[t] = g_A1[i][t];
        __syncthreads();
        if (t < 256) {
            int e = t;
            const float scale = 0.17677669529663687f;
#pragma unroll
            for (int h = 0; h < 8; h++) {
                float s = 0.f;
#pragma unroll
                for (int dd = 0; dd < 32; dd++) s += a1[h * 32 + dd] * g_WkT[h * 32 + dd][e];
                g_Wbig[i][h * 256 + e] = scale * s;
            }
            if (e < 8) {
                float s = 0.f;
                for (int dd = 0; dd < 32; dd++) s += a1[e * 32 + dd] * bqkv[256 + e * 32 + dd];
                g_Wbig[i][2048 + e] = scale * s;
            }
        }
    } else {                                // T3 rows
        int j = blk - 514;
        __shared__ float t2[256];
        if (t < 256) t2[t] = g_T2ext[j][t];
        __syncthreads();
        if (t < 256) {
            float s = 0.f;
            for (int k = 0; k < 256; k++) s += t2[k] * g_WpkT[k][t];
            g_T3ext[j][t] = s;
        } else if (t == 256) {
            float s = 0.f;
            for (int k = 0; k < 256; k++) s += t2[k] * bpk[k];
            g_T3ext[j][256] = s;
        }
    }
}

// ======== pG ========
__global__ void pG(const float* __restrict__ Wqkv, const float* __restrict__ bqkv) {
    int he = blockIdx.x, t = threadIdx.x;
    __shared__ float sw[256];
    if (he < 2048) {
        int h = he >> 8, e = he & 255;
        if (t < 32) sw[t] = Wqkv[e * 768 + 512 + h * 32 + t];
        __syncthreads();
        if (t < 257) {
            float s = 0.f;
            int jb = h * 32;
#pragma unroll
            for (int jl = 0; jl < 32; jl++) s += sw[jl] * g_T3ext[jb + jl][t];
            g_G[he][t] = s;
        }
    } else {
        if (t < 256) sw[t] = bqkv[512 + t];
        __syncthreads();
        if (t < 257) {
            float s = g_T3ext[256][t];
            for (int j = 0; j < 256; j++) s += sw[j] * g_T3ext[j][t];
            g_G[2048][t] = s;
        }
    }
}

// ======== GEMM1: qkflat = cat @ Wbig ========
__global__ void __launch_bounds__(256) k_gemm1() {
    int n0 = blockIdx.x * 128, m0 = blockIdx.y * 32;
    int t = threadIdx.x, tx = t & 31, ty = t >> 5;
    __shared__ __align__(16) float As[32][33];
    __shared__ __align__(16) float Bs[32][128];
    ull acc2[4][2];
#pragma unroll
    for (int i = 0; i < 4; i++) { acc2[i][0] = 0ull; acc2[i][1] = 0ull; }
    for (int k0 = 0; k0 < K1; k0 += 32) {
#pragma unroll
        for (int l = 0; l < 4; l++) {
            int idx = t + 256 * l;
            As[idx >> 5][idx & 31] = g_cat[m0 + (idx >> 5)][k0 + (idx & 31)];
        }
#pragma unroll
        for (int l = 0; l < 4; l++) {
            int idx = t + 256 * l;
            int r = idx >> 5, c = idx & 31;
            *(float4*)&Bs[r][c * 4] = *(const float4*)&g_Wbig[k0 + r][n0 + c * 4];
        }
        __syncthreads();
#pragma unroll
        for (int kk = 0; kk < 32; kk++) {
            ulonglong2 bv = *(const ulonglong2*)&Bs[kk][tx * 4];
#pragma unroll
            for (int i = 0; i < 4; i++) {
                float a = As[ty * 4 + i][kk];
                ull ad = pk2(a, a);
                fma2(acc2[i][0], ad, bv.x);
                fma2(acc2[i][1], ad, bv.y);
            }
        }
        __syncthreads();
    }
#pragma unroll
    for (int i = 0; i < 4; i++) {
        float4 v;
        upk2(acc2[i][0], v.x, v.y);
        upk2(acc2[i][1], v.z, v.w);
        *(float4*)&g_qkflat[m0 + ty * 4 + i][n0 + tx * 4] = v;
    }
}

// ======== K2: flash attention over x, merge fused into last block ========
__global__ void __launch_bounds__(256, 2)
k_attn(const float* __restrict__ x) {
    int seg = blockIdx.x, b = blockIdx.y;
    int t = threadIdx.x, lane = t & 31, w = t >> 5;
    __shared__ __align__(16) float xs[SUBN * XPITCH];
    __shared__ __align__(16) float ss[SUBN][12];
    __shared__ float alpha_s[8];
    __shared__ int s_last;

    ull qkr2[8][4];
#pragma unroll
    for (int h = 0; h < 8; h++) {
        float4 q0 = *(const float4*)&g_qkflat[b][h * 256 + lane * 8];
        float4 q1 = *(const float4*)&g_qkflat[b][h * 256 + lane * 8 + 4];
        qkr2[h][0] = pk2(q0.x, q0.y); qkr2[h][1] = pk2(q0.z, q0.w);
        qkr2[h][2] = pk2(q1.x, q1.y); qkr2[h][3] = pk2(q1.z, q1.w);
    }
    float sbw = g_qkflat[b][2048 + w];  // bias for head w (softmax phase)

    int dimbase = (w & 3) * 64;
    int nq0 = (w >> 2) * 16;
    ull acc2[8];
#pragma unroll
    for (int h = 0; h < 8; h++) acc2[h] = 0ull;
    float mstate = NEG_BIG, lstate = 0.f;

    int n0 = seg * NSEG;
    for (int c = 0; c < NSEG / SUBN; c++) {
        int nb = n0 + c * SUBN;
        __syncthreads();
        {
            const float4* src = (const float4*)(x + ((size_t)b * Nc + nb) * Ec);
#pragma unroll
            for (int i = 0; i < 8; i++) {
                int g = t + 256 * i;
                int row = g >> 6, c4 = g & 63;
                *(float4*)&xs[row * XPITCH + c4 * 4] = src[row * 64 + c4];
            }
        }
        __syncthreads();

        // ---- scores (16-shfl reduction, no bias yet) ----
#pragma unroll
        for (int i = 0; i < 4; i++) {
            int nl = w * 4 + i;
            float4 xv0 = *(const float4*)&xs[nl * XPITCH + lane * 8];
            float4 xv1 = *(const float4*)&xs[nl * XPITCH + lane * 8 + 4];
            ull x2[4] = {pk2(xv0.x, xv0.y), pk2(xv0.z, xv0.w),
                         pk2(xv1.x, xv1.y), pk2(xv1.z, xv1.w)};
            float s[8];
#pragma unroll
            for (int h = 0; h < 8; h++) {
                ull s2 = 0ull;
#pragma unroll
                for (int j = 0; j < 4; j++) fma2(s2, qkr2[h][j], x2[j]);
                float lo, hi;
                upk2(s2, lo, hi);
                s[h] = lo + hi;
            }
            float v = red8(s, lane);
            if ((lane & 3) == 0) {
                int h = lane >> 2;
                ss[nl][h] = g_mask[b][nb + nl] ? NEG_BIG : v;
            }
        }
        __syncthreads();

        // ---- online softmax: warp w owns head w ----
        {
            float raw = ss[lane][w];
            float v = (raw < -1e29f) ? NEG_BIG : raw + sbw;
            float mx = v;
#pragma unroll
            for (int off = 16; off; off >>= 1)
                mx = fmaxf(mx, __shfl_xor_sync(0xffffffffu, mx, off));
            float mnew = fmaxf(mstate, mx);
            float alpha = (mstate > 0.5f * NEG_BIG) ? expf(mstate - mnew) : 0.f;
            float p = (v > 0.5f * NEG_BIG) ? expf(v - mnew) : 0.f;
            ss[lane][w] = p;
            float ps = p;
#pragma unroll
            for (int off = 16; off; off >>= 1)
                ps += __shfl_xor_sync(0xffffffffu, ps, off);
            lstate = lstate * alpha + ps;
            mstate = mnew;
            if (lane == 0) alpha_s[w] = alpha;
        }
        __syncthreads();

        // ---- acc: dims-sliced, x read once ----
        {
            ull ad[8];
#pragma unroll
            for (int h = 0; h < 8; h++) {
                float a = alpha_s[h];
                ad[h] = pk2(a, a);
            }
#pragma unroll
            for (int h = 0; h < 8; h++) acc2[h] = mul2(acc2[h], ad[h]);
            for (int r = 0; r < 16; r++) {
                int n = nq0 + r;
                float2 xv = *(const float2*)&xs[n * XPITCH + dimbase + lane * 2];
                ull xp = pk2(xv.x, xv.y);
                float4 pa = *(const float4*)&ss[n][0];
                float4 pb = *(const float4*)&ss[n][4];
                fma2(acc2[0], pk2(pa.x, pa.x), xp);
                fma2(acc2[1], pk2(pa.y, pa.y), xp);
                fma2(acc2[2], pk2(pa.z, pa.z), xp);
                fma2(acc2[3], pk2(pa.w, pa.w), xp);
                fma2(acc2[4], pk2(pb.x, pb.x), xp);
                fma2(acc2[5], pk2(pb.y, pb.y), xp);
                fma2(acc2[6], pk2(pb.z, pb.z), xp);
                fma2(acc2[7], pk2(pb.w, pb.w), xp);
            }
        }
    }

    if (lane == 0) {
        g_part[b][seg][w][0] = mstate;
        g_part[b][seg][w][1] = lstate;
    }

    // combine row-halves, write partials
    __syncthreads();
    float* buf = xs;
    if (w >= 4) {
        int ds = w & 3;
#pragma unroll
        for (int h = 0; h < 8; h++) {
            float lo, hi;
            upk2(acc2[h], lo, hi);
            buf[(ds * 8 + h) * 64 + lane * 2] = lo;
            buf[(ds * 8 + h) * 64 + lane * 2 + 1] = hi;
        }
    }
    __syncthreads();
    if (w < 4) {
        int ds = w;
#pragma unroll
        for (int h = 0; h < 8; h++) {
            float lo, hi;
            upk2(acc2[h], lo, hi);
            lo += buf[(ds * 8 + h) * 64 + lane * 2];
            hi += buf[(ds * 8 + h) * 64 + lane * 2 + 1];
            g_part[b][seg][h][2 + ds * 64 + lane * 2] = lo;
            g_part[b][seg][h][2 + ds * 64 + lane * 2 + 1] = hi;
        }
    }

    // ---- last block for this b performs the merge -> ctxA ----
    __threadfence();
    __syncthreads();
    if (t == 0) {
        int old = atomicAdd(&g_syncnt[b], 1);
        s_last = (old == SEG - 1) ? 1 : 0;
        if (s_last) g_syncnt[b] = 0;
    }
    __syncthreads();
    if (s_last) {
        __threadfence();
#pragma unroll
        for (int h = 0; h < 8; h++) {
            float M = NEG_BIG;
#pragma unroll
            for (int s = 0; s < SEG; s++) M = fmaxf(M, g_part[b][s][h][0]);
            float L = 0.f, a = 0.f;
#pragma unroll
            for (int s = 0; s < SEG; s++) {
                float ms = g_part[b][s][h][0];
                float wg = (ms > 0.5f * NEG_BIG) ? expf(ms - M) : 0.f;
                L += wg * g_part[b][s][h][1];
                a += wg * g_part[b][s][h][2 + t];
            }
            g_ctxA[b][h * 256 + t] = a / L;
        }
        if (t == 0) g_ctxA[b][2048] = 1.f;
    }
}

// ======== GEMM2 (split-K): qpkpart = ctxA @ G ========
__global__ void __launch_bounds__(256) k_gemm2() {
    int n0 = blockIdx.x * 96, m0 = blockIdx.y * 32, s = blockIdx.z;
    int c0 = (s * 65) / 8, c1 = ((s + 1) * 65) / 8;
    int t = threadIdx.x, tx = t & 31, ty = t >> 5;
    __shared__ __align__(16) float As[32][33];
    __shared__ __align__(16) float Bs[32][96];
    float acc[4][3] = {};
    for (int c = c0; c < c1; c++) {
        int k0 = c * 32;
#pragma unroll
        for (int l = 0; l < 4; l++) {
            int idx = t + 256 * l;
            As[idx >> 5][idx & 31] = g_ctxA[m0 + (idx >> 5)][k0 + (idx & 31)];
        }
#pragma unroll
        for (int l = 0; l < 3; l++) {
            int idx = t + 256 * l;
            int r = idx / 24, cc = idx % 24;
            *(float4*)&Bs[r][cc * 4] = *(const float4*)&g_G[k0 + r][n0 + cc * 4];
        }
        __syncthreads();
#pragma unroll
        for (int kk = 0; kk < 32; kk++) {
            float a0 = As[ty * 4 + 0][kk], a1 = As[ty * 4 + 1][kk];
            float a2 = As[ty * 4 + 2][kk], a3 = As[ty * 4 + 3][kk];
            float b0 = Bs[kk][tx * 3 + 0], b1 = Bs[kk][tx * 3 + 1], b2 = Bs[kk][tx * 3 + 2];
            acc[0][0] += a0 * b0; acc[0][1] += a0 * b1; acc[0][2] += a0 * b2;
            acc[1][0] += a1 * b0; acc[1][1] += a1 * b1; acc[1][2] += a1 * b2;
            acc[2][0] += a2 * b0; acc[2][1] += a2 * b1; acc[2][2] += a2 * b2;
            acc[3][0] += a3 * b0; acc[3][1] += a3 * b1; acc[3][2] += a3 * b2;
        }
        __syncthreads();
    }
#pragma unroll
    for (int i = 0; i < 4; i++)
#pragma unroll
        for (int j = 0; j < 3; j++)
            g_qpkpart[s][m0 + ty * 4 + i][n0 + tx * 3 + j] = acc[i][j];
}

// ======== pointer logits + softmax + argmax + state for NEXT step ========
__global__ void __launch_bounds__(1024) k_pointsel(
    const float* __restrict__ x, const float* __restrict__ demand,
    float* __restrict__ out, int t_step, int write_route) {
    int b = blockIdx.x;
    int t = threadIdx.x, lane = t & 31, w = t >> 5;
    __shared__ float qs[Ec];
    __shared__ float u_s[Nc];
    __shared__ float s_ub;
    __shared__ float rv[32];
    __shared__ int ri[32];
    __shared__ float rs[32];
    __shared__ int redm[32];
    __shared__ int s_node;
    __shared__ float s_max, s_sum;

    float cap_old = g_cap[b];
    float cnt_old = g_cnt[b];

    if (t < 256) {
        float a = 0.f;
#pragma unroll
        for (int s = 0; s < 8; s++) a += g_qpkpart[s][b][t];
        qs[t] = a;
    } else if (t == 256) {
        float u = 0.f;
#pragma unroll
        for (int s = 0; s < 8; s++) u += g_qpkpart[s][b][256];
        s_ub = u;
    }
    __syncthreads();
    float ub = s_ub;
    ull q2[4];
    {
        float4 a0 = *(const float4*)&qs[lane * 8];
        float4 a1 = *(const float4*)&qs[lane * 8 + 4];
        q2[0] = pk2(a0.x, a0.y); q2[1] = pk2(a0.z, a0.w);
        q2[2] = pk2(a1.x, a1.y); q2[3] = pk2(a1.z, a1.w);
    }

    // phase A: 32 warps x 32 rows, 8-row batches
    int rbase = w * 32;
#pragma unroll
    for (int bch = 0; bch < 4; bch++) {
        float sr[8];
#pragma unroll
        for (int r = 0; r < 8; r++) {
            int n = rbase + bch * 8 + r;
            const float4* xr = (const float4*)(x + ((size_t)b * Nc + n) * Ec);
            float4 a0 = xr[lane * 2], a1 = xr[lane * 2 + 1];
            ull acc = 0ull;
            fma2(acc, pk2(a0.x, a0.y), q2[0]);
            fma2(acc, pk2(a0.z, a0.w), q2[1]);
            fma2(acc, pk2(a1.x, a1.y), q2[2]);
            fma2(acc, pk2(a1.z, a1.w), q2[3]);
            float lo, hi;
            upk2(acc, lo, hi);
            sr[r] = lo + hi;
        }
        float v = red8(sr, lane);
        if ((lane & 3) == 0) {
            int n = rbase + bch * 8 + (lane >> 2);
            u_s[n] = g_mask[b][n] ? NEG_BIG : CLIPC * tanhf(v + ub);
        }
    }
    __syncthreads();

    // phase B: argmax (first index), softmax, output
    float uv = u_s[t];
    float bv = uv;
    int bi = t;
#pragma unroll
    for (int off = 16; off; off >>= 1) {
        float ov = __shfl_xor_sync(0xffffffffu, bv, off);
        int oi = __shfl_xor_sync(0xffffffffu, bi, off);
        if (ov > bv || (ov == bv && oi < bi)) { bv = ov; bi = oi; }
    }
    if (lane == 0) { rv[w] = bv; ri[w] = bi; }
    __syncthreads();
    if (w == 0) {
        float v2 = rv[lane];
        int i2 = ri[lane];
#pragma unroll
        for (int off = 16; off; off >>= 1) {
            float ov = __shfl_xor_sync(0xffffffffu, v2, off);
            int oi = __shfl_xor_sync(0xffffffffu, i2, off);
            if (ov > v2 || (ov == v2 && oi < i2)) { v2 = ov; i2 = oi; }
        }
        if (lane == 0) { s_max = v2; s_node = i2; }
    }
    __syncthreads();
    float mx = s_max;
    int node = s_node;

    float p = expf(uv - mx);
    float ps = p;
#pragma unroll
    for (int off = 16; off; off >>= 1) ps += __shfl_xor_sync(0xffffffffu, ps, off);
    if (lane == 0) rs[w] = ps;
    __syncthreads();
    if (w == 0) {
        float s = rs[lane];
#pragma unroll
        for (int off = 16; off; off >>= 1) s += __shfl_xor_sync(0xffffffffu, s, off);
        if (lane == 0) s_sum = s;
    }
    __syncthreads();
    float inv = 1.f / s_sum;
    out[(size_t)t_step * Bc * Nc + (size_t)b * Nc + t] = p * inv;

    // ---- state update for next step ----
    float dnode = demand[(size_t)b * Nc + node];
    float cap_new = cap_old - dnode;
    int nz = (node != 0);
    float cnt_new = cnt_old - (nz ? 1.f : 0.f);

    int vo = g_visited[b][t];
    __syncthreads();  // all reads of g_visited done before the write below
    if (t == 0) {
        if (write_route) out[(size_t)Tc * Bc * Nc + (size_t)t_step * Bc + b] = (float)node;
        g_cap[b] = cap_new;
        g_cur[b] = node;
        g_cnt[b] = cnt_new;
        if (nz) g_visited[b][node] = 1;
    }
    int vis = vo | ((t == node) ? nz : 0);
    int m = vis | (demand[(size_t)b * Nc + t] > cap_new);
    if (t == 0) m = (node == 0) ? 1 : m;
    g_mask[b][t] = (unsigned char)m;
    int am = __all_sync(0xffffffffu, m);
    if (lane == 0) redm[w] = am;

    float xn = x[((size_t)b * Nc + node) * Ec + (t & 255)];
    if (t < 256) {
        float sx = g_sumx[b][t] - (nz ? xn : 0.f);
        g_sumx[b][t] = sx;
        g_cat[b][t] = sx / cnt_new;
        g_cat[b][256 + t] = xn;
    } else if (t >= 514 && t < 544) {
        g_cat[b][t] = 0.f;
    }
    if (t == 0) { g_cat[b][512] = cap_new; g_cat[b][513] = 1.f; }
    __syncthreads();
    if (t == 0) {
        int a = 1;
#pragma unroll
        for (int k = 0; k < 32; k++) a &= redm[k];
        if (a) g_mask[b][0] = 0;
    }
}

// ---------------- launch ----------------
extern "C" void kernel_launch(void* const* d_in, const int* in_sizes, int n_in,
                              void* d_out, int out_size) {
    const float* x      = (const float*)d_in[0];
    const float* demand = (const float*)d_in[1];
    const float* cap0   = (const float*)d_in[2];
    const float* Wc     = (const float*)d_in[3];
    const float* bc     = (const float*)d_in[4];
    const float* Wqkv   = (const float*)d_in[5];
    const float* bqkv   = (const float*)d_in[6];
    const float* Wo     = (const float*)d_in[7];
    const float* bo     = (const float*)d_in[8];
    const float* Wpq    = (const float*)d_in[9];
    const float* bpq    = (const float*)d_in[10];
    const float* Wpk    = (const float*)d_in[11];
    const float* bpk    = (const float*)d_in[12];
    float* out = (float*)d_out;
    int write_route = (out_size > Tc * Bc * Nc) ? 1 : 0;

    kP0a<<<1024, 256>>>(x, cap0, Wqkv, Wpk);
    kP0b<<<1027, 256>>>(x, demand, cap0, Wc, bc, Wqkv, bqkv, Wo, bo, Wpq, bpq);
    kPW<<<771, 288>>>(bqkv, bpk);
    pG<<<2049, 288>>>(Wqkv, bqkv);

    for (int t = 0; t < Tc; t++) {
        k_gemm1<<<dim3(17, 8), 256>>>();
        k_attn<<<dim3(SEG, Bc), 256>>>(x);
        k_gemm2<<<dim3(3, 8, 8), 256>>>();
        k_pointsel<<<Bc, 1024>>>(x, demand, out, t, write_route);
    }
}

// round 7
// speedup vs baseline: 2.2727x; 1.0732x over previous
#include <cuda_runtime.h>
#include <math.h>

#define Bc 256
#define Nc 1024
#define Ec 256
#define Hc 8
#define Tc 64
#define SEG 8
#define NSEG 128
#define SUBN 32
#define XPITCH 260
#define NCH (NSEG / SUBN)
#define XBUF_FLOATS (SUBN * XPITCH)
#define NEG_BIG (-1e30f)
#define CLIPC 10.0f

#define K1 544
#define N1 2176
#define K2 2080
#define N2 288

typedef unsigned long long ull;

// ---------------- f32x2 packed helpers ----------------
__device__ __forceinline__ ull pk2(float lo, float hi) {
    ull r; asm("mov.b64 %0, {%1, %2};" : "=l"(r) : "f"(lo), "f"(hi)); return r;
}
__device__ __forceinline__ void upk2(ull v, float& lo, float& hi) {
    asm("mov.b64 {%0, %1}, %2;" : "=f"(lo), "=f"(hi) : "l"(v));
}
__device__ __forceinline__ void fma2(ull& d, ull a, ull b) {
    asm("fma.rn.f32x2 %0, %1, %2, %0;" : "+l"(d) : "l"(a), "l"(b));
}
__device__ __forceinline__ ull mul2(ull a, ull b) {
    ull r; asm("mul.rn.f32x2 %0, %1, %2;" : "=l"(r) : "l"(a), "l"(b)); return r;
}

// 8-value cross-warp sum reduction with redistribution: 16 shfl.
// On return, lane 4*k (k=0..7) holds the full sum of value k.
__device__ __forceinline__ float red8(float s[8], int lane) {
#pragma unroll
    for (int j = 0; j < 8; j++) s[j] += __shfl_xor_sync(0xffffffffu, s[j], 16);
    float k4[4];
    int hi16 = lane & 16;
#pragma unroll
    for (int j = 0; j < 4; j++) k4[j] = hi16 ? s[j + 4] : s[j];
#pragma unroll
    for (int j = 0; j < 4; j++) k4[j] += __shfl_xor_sync(0xffffffffu, k4[j], 8);
    float c0 = (lane & 8) ? k4[2] : k4[0];
    float c1 = (lane & 8) ? k4[3] : k4[1];
    c0 += __shfl_xor_sync(0xffffffffu, c0, 4);
    c1 += __shfl_xor_sync(0xffffffffu, c1, 4);
    float v = (lane & 4) ? c1 : c0;
    v += __shfl_xor_sync(0xffffffffu, v, 2);
    v += __shfl_xor_sync(0xffffffffu, v, 1);
    return v;
}

// ---------------- persistent device state ----------------
__device__ float g_sumx[Bc][Ec];
__device__ float g_cnt[Bc];
__device__ float g_cap[Bc];
__device__ int   g_cur[Bc];
__device__ unsigned char g_visited[Bc][Nc];
__device__ unsigned char g_mask[Bc][Nc];
__device__ float g_part[Bc][SEG][Hc][Ec + 2];
__device__ int   g_syncnt[Bc];

__device__ float g_A1[514][256];
__device__ float g_WkT[256][256];
__device__ float g_Wbig[K1][N1];
__device__ float g_cat[Bc][K1];
__device__ float g_qkflat[Bc][N1];
__device__ float g_T2ext[257][256];
__device__ float g_WpkT[256][256];
__device__ float g_T3ext[257][288];
__device__ float g_G[K2][N2];
__device__ float g_ctxA[Bc][K2];
__device__ float g_qpkpart[8][Bc][N2];

// ======== P1: everything that depends only on inputs ========
// blk 0..255   : per-b init (sumx, visited, counters) + step-0 mask/cat
// blk 256..511 : WkT
// blk 512..767 : WpkT
// blk 768..1281: A1 = [Wc;bc] @ Wq (+bq)
// blk 1282..1538: T2 = [Wo;bo] @ Wpq (+bpq)
// blk 1539..1794: zero pads of Wbig / G / ctxA
__global__ void kP1(const float* __restrict__ x, const float* __restrict__ demand,
                    const float* __restrict__ cap0,
                    const float* __restrict__ Wc, const float* __restrict__ bc,
                    const float* __restrict__ Wqkv, const float* __restrict__ bqkv,
                    const float* __restrict__ Wo, const float* __restrict__ bo,
                    const float* __restrict__ Wpq, const float* __restrict__ bpq,
                    const float* __restrict__ Wpk) {
    int blk = blockIdx.x, t = threadIdx.x;
    if (blk < 256) {
        int b = blk;
        __shared__ int red[8];
        const float* xb = x + (size_t)b * Nc * Ec;
        float s = 0.f;
        for (int n = 0; n < Nc; n++) s += xb[(size_t)n * Ec + t];
        g_sumx[b][t] = s;
        for (int i = t; i < Nc; i += 256) g_visited[b][i] = 0;
        float cap = cap0[b];
        if (t == 0) {
            g_cnt[b] = (float)Nc;
            g_cap[b] = cap;
            g_cur[b] = 0;
            g_syncnt[b] = 0;
        }
        g_cat[b][t] = s / (float)Nc;
        g_cat[b][256 + t] = xb[t];
        if (t == 0) { g_cat[b][512] = cap; g_cat[b][513] = 1.f; }
        if (t < 30) g_cat[b][514 + t] = 0.f;
        int allm = 1;
        for (int n = t; n < Nc; n += 256) {
            int m = (demand[(size_t)b * Nc + n] > cap);
            if (n == 0) m = 1;
            g_mask[b][n] = (unsigned char)m;
            allm &= m;
        }
        allm = __all_sync(0xffffffffu, allm);
        if ((t & 31) == 0) red[t >> 5] = allm;
        __syncthreads();
        if (t == 0) {
            int a = 1;
            for (int w = 0; w < 8; w++) a &= red[w];
            if (a) g_mask[b][0] = 0;
        }
    } else if (blk < 512) {
        int d = blk - 256;
        g_WkT[d][t] = Wqkv[t * 768 + 256 + d];
    } else if (blk < 768) {
        int j2 = blk - 512;
        g_WpkT[j2][t] = Wpk[t * 256 + j2];
    } else if (blk < 1282) {
        int i = blk - 768;
        __shared__ float wrow[256];
        wrow[t] = (i < 513) ? Wc[i * 256 + t] : bc[t];
        __syncthreads();
        float s = (i == 513) ? bqkv[t] : 0.f;
        for (int e = 0; e < 256; e++) s += wrow[e] * Wqkv[e * 768 + t];
        g_A1[i][t] = s;
    } else if (blk < 1539) {
        int i = blk - 1282;
        __shared__ float wrow[256];
        wrow[t] = (i < 256) ? Wo[i * 256 + t] : bo[t];
        __syncthreads();
        float s = (i == 256) ? bpq[t] : 0.f;
        for (int k = 0; k < 256; k++) s += wrow[k] * Wpq[k * 256 + t];
        g_T2ext[i][t] = s;
    } else {
        int idx = (blk - 1539) * 256 + t;
        float* w = &g_Wbig[0][0];
        for (int i = idx; i < K1 * N1; i += 65536) w[i] = 0.f;
        float* g = &g_G[0][0];
        for (int i = idx; i < K2 * N2; i += 65536) g[i] = 0.f;
        for (int i = idx; i < Bc * 31; i += 65536) {
            int b = i / 31, j = i % 31;
            g_ctxA[b][2049 + j] = 0.f;
        }
    }
}

// ======== P2: Wbig (needs A1, WkT) + T3 (needs T2, WpkT) ========
__global__ void kP2(const float* __restrict__ bqkv, const float* __restrict__ bpk) {
    int blk = blockIdx.x, t = threadIdx.x;  // 288 threads
    if (blk < 514) {
        int i = blk;
        __shared__ float a1[256];
        if (t < 256) a1[t] = g_A1[i][t];
        __syncthreads();
        if (t < 256) {
            int e = t;
            const float scale = 0.17677669529663687f;
#pragma unroll
            for (int h = 0; h < 8; h++) {
                float s = 0.f;
#pragma unroll
                for (int dd = 0; dd < 32; dd++) s += a1[h * 32 + dd] * g_WkT[h * 32 + dd][e];
                g_Wbig[i][h * 256 + e] = scale * s;
            }
            if (e < 8) {
                float s = 0.f;
                for (int dd = 0; dd < 32; dd++) s += a1[e * 32 + dd] * bqkv[256 + e * 32 + dd];
                g_Wbig[i][2048 + e] = scale * s;
            }
        }
    } else {
        int j = blk - 514;
        __shared__ float t2[256];
        if (t < 256) t2[t] = g_T2ext[j][t];
        __syncthreads();
        if (t < 256) {
            float s = 0.f;
            for (int k = 0; k < 256; k++) s += t2[k] * g_WpkT[k][t];
            g_T3ext[j][t] = s;
        } else if (t == 256) {
            float s = 0.f;
            for (int k = 0; k < 256; k++) s += t2[k] * bpk[k];
            g_T3ext[j][256] = s;
        }
    }
}

// ======== pG: G = [Wv;bv]-fold @ T3 (needs T3; only used by gemm2) ========
__global__ void pG(const float* __restrict__ Wqkv, const float* __restrict__ bqkv) {
    int he = blockIdx.x, t = threadIdx.x;
    __shared__ float sw[256];
    if (he < 2048) {
        int h = he >> 8, e = he & 255;
        if (t < 32) sw[t] = Wqkv[e * 768 + 512 + h * 32 + t];
        __syncthreads();
        if (t < 257) {
            float s = 0.f;
            int jb = h * 32;
#pragma unroll
            for (int jl = 0; jl < 32; jl++) s += sw[jl] * g_T3ext[jb + jl][t];
            g_G[he][t] = s;
        }
    } else {
        if (t < 256) sw[t] = bqkv[512 + t];
        __syncthreads();
        if (t < 257) {
            float s = g_T3ext[256][t];
            for (int j = 0; j < 256; j++) s += sw[j] * g_T3ext[j][t];
            g_G[2048][t] = s;
        }
    }
}

// ======== GEMM1: qkflat = cat @ Wbig ========
__global__ void __launch_bounds__(256) k_gemm1() {
    int n0 = blockIdx.x * 128, m0 = blockIdx.y * 32;
    int t = threadIdx.x, tx = t & 31, ty = t >> 5;
    __shared__ __align__(16) float As[32][33];
    __shared__ __align__(16) float Bs[32][128];
    ull acc2[4][2];
#pragma unroll
    for (int i = 0; i < 4; i++) { acc2[i][0] = 0ull; acc2[i][1] = 0ull; }
    for (int k0 = 0; k0 < K1; k0 += 32) {
#pragma unroll
        for (int l = 0; l < 4; l++) {
            int idx = t + 256 * l;
            As[idx >> 5][idx & 31] = g_cat[m0 + (idx >> 5)][k0 + (idx & 31)];
        }
#pragma unroll
        for (int l = 0; l < 4; l++) {
            int idx = t + 256 * l;
            int r = idx >> 5, c = idx & 31;
            *(float4*)&Bs[r][c * 4] = *(const float4*)&g_Wbig[k0 + r][n0 + c * 4];
        }
        __syncthreads();
#pragma unroll
        for (int kk = 0; kk < 32; kk++) {
            ulonglong2 bv = *(const ulonglong2*)&Bs[kk][tx * 4];
#pragma unroll
            for (int i = 0; i < 4; i++) {
                float a = As[ty * 4 + i][kk];
                ull ad = pk2(a, a);
                fma2(acc2[i][0], ad, bv.x);
                fma2(acc2[i][1], ad, bv.y);
            }
        }
        __syncthreads();
    }
#pragma unroll
    for (int i = 0; i < 4; i++) {
        float4 v;
        upk2(acc2[i][0], v.x, v.y);
        upk2(acc2[i][1], v.z, v.w);
        *(float4*)&g_qkflat[m0 + ty * 4 + i][n0 + tx * 4] = v;
    }
}

// ======== K2: flash attention over x, cp.async double-buffered ========
__global__ void __launch_bounds__(256, 2)
k_attn(const float* __restrict__ x) {
    extern __shared__ __align__(16) float dyn[];
    float* xsb[2] = {dyn, dyn + XBUF_FLOATS};
    float (*ss)[12] = (float (*)[12])(dyn + 2 * XBUF_FLOATS);
    float* alpha_s = dyn + 2 * XBUF_FLOATS + 32 * 12;
    __shared__ int s_last;

    int seg = blockIdx.x, b = blockIdx.y;
    int t = threadIdx.x, lane = t & 31, w = t >> 5;

    ull qkr2[8][4];
#pragma unroll
    for (int h = 0; h < 8; h++) {
        float4 q0 = *(const float4*)&g_qkflat[b][h * 256 + lane * 8];
        float4 q1 = *(const float4*)&g_qkflat[b][h * 256 + lane * 8 + 4];
        qkr2[h][0] = pk2(q0.x, q0.y); qkr2[h][1] = pk2(q0.z, q0.w);
        qkr2[h][2] = pk2(q1.x, q1.y); qkr2[h][3] = pk2(q1.z, q1.w);
    }
    float sbw = g_qkflat[b][2048 + w];

    int dimbase = (w & 3) * 64;
    int nq0 = (w >> 2) * 16;
    ull acc2[8];
#pragma unroll
    for (int h = 0; h < 8; h++) acc2[h] = 0ull;
    float mstate = NEG_BIG, lstate = 0.f;

    int n0 = seg * NSEG;
    unsigned xs_smem = (unsigned)__cvta_generic_to_shared(dyn);
    int srow = t >> 6, sc4 = t & 63;       // this thread's 8 staging slots

    // prologue: stage chunk 0 into buf 0
    {
        const float4* src = (const float4*)(x + ((size_t)b * Nc + n0) * Ec);
#pragma unroll
        for (int i = 0; i < 8; i++) {
            int row = srow + i * 4;
            unsigned daddr = xs_smem + (unsigned)((row * XPITCH + sc4 * 4) * 4);
            asm volatile("cp.async.cg.shared.global [%0], [%1], 16;"
                         :: "r"(daddr), "l"(src + row * 64 + sc4));
        }
        asm volatile("cp.async.commit_group;");
    }

    for (int c = 0; c < NCH; c++) {
        int cur = c & 1;
        int nb = n0 + c * SUBN;
        if (c < NCH - 1) {  // prefetch next chunk into other buffer
            const float4* src = (const float4*)(x + ((size_t)b * Nc + nb + SUBN) * Ec);
            unsigned bufo = xs_smem + (unsigned)((1 - cur) * XBUF_FLOATS * 4);
#pragma unroll
            for (int i = 0; i < 8; i++) {
                int row = srow + i * 4;
                unsigned daddr = bufo + (unsigned)((row * XPITCH + sc4 * 4) * 4);
                asm volatile("cp.async.cg.shared.global [%0], [%1], 16;"
                             :: "r"(daddr), "l"(src + row * 64 + sc4));
            }
            asm volatile("cp.async.commit_group;");
            asm volatile("cp.async.wait_group 1;" ::: "memory");
        } else {
            asm volatile("cp.async.wait_group 0;" ::: "memory");
        }
        __syncthreads();
        const float* xs = xsb[cur];

        // ---- scores ----
#pragma unroll
        for (int i = 0; i < 4; i++) {
            int nl = w * 4 + i;
            float4 xv0 = *(const float4*)&xs[nl * XPITCH + lane * 8];
            float4 xv1 = *(const float4*)&xs[nl * XPITCH + lane * 8 + 4];
            ull x2[4] = {pk2(xv0.x, xv0.y), pk2(xv0.z, xv0.w),
                         pk2(xv1.x, xv1.y), pk2(xv1.z, xv1.w)};
            float s[8];
#pragma unroll
            for (int h = 0; h < 8; h++) {
                ull s2 = 0ull;
#pragma unroll
                for (int j = 0; j < 4; j++) fma2(s2, qkr2[h][j], x2[j]);
                float lo, hi;
                upk2(s2, lo, hi);
                s[h] = lo + hi;
            }
            float v = red8(s, lane);
            if ((lane & 3) == 0) {
                int h = lane >> 2;
                ss[nl][h] = g_mask[b][nb + nl] ? NEG_BIG : v;
            }
        }
        __syncthreads();

        // ---- online softmax: warp w owns head w ----
        {
            float raw = ss[lane][w];
            float v = (raw < -1e29f) ? NEG_BIG : raw + sbw;
            float mx = v;
#pragma unroll
            for (int off = 16; off; off >>= 1)
                mx = fmaxf(mx, __shfl_xor_sync(0xffffffffu, mx, off));
            float mnew = fmaxf(mstate, mx);
            float alpha = (mstate > 0.5f * NEG_BIG) ? expf(mstate - mnew) : 0.f;
            float p = (v > 0.5f * NEG_BIG) ? expf(v - mnew) : 0.f;
            ss[lane][w] = p;
            float ps = p;
#pragma unroll
            for (int off = 16; off; off >>= 1)
                ps += __shfl_xor_sync(0xffffffffu, ps, off);
            lstate = lstate * alpha + ps;
            mstate = mnew;
            if (lane == 0) alpha_s[w] = alpha;
        }
        __syncthreads();

        // ---- acc: dims-sliced, x read once ----
        {
            ull ad[8];
#pragma unroll
            for (int h = 0; h < 8; h++) {
                float a = alpha_s[h];
                ad[h] = pk2(a, a);
            }
#pragma unroll
            for (int h = 0; h < 8; h++) acc2[h] = mul2(acc2[h], ad[h]);
            for (int r = 0; r < 16; r++) {
                int n = nq0 + r;
                float2 xv = *(const float2*)&xs[n * XPITCH + dimbase + lane * 2];
                ull xp = pk2(xv.x, xv.y);
                float4 pa = *(const float4*)&ss[n][0];
                float4 pb = *(const float4*)&ss[n][4];
                fma2(acc2[0], pk2(pa.x, pa.x), xp);
                fma2(acc2[1], pk2(pa.y, pa.y), xp);
                fma2(acc2[2], pk2(pa.z, pa.z), xp);
                fma2(acc2[3], pk2(pa.w, pa.w), xp);
                fma2(acc2[4], pk2(pb.x, pb.x), xp);
                fma2(acc2[5], pk2(pb.y, pb.y), xp);
                fma2(acc2[6], pk2(pb.z, pb.z), xp);
                fma2(acc2[7], pk2(pb.w, pb.w), xp);
            }
        }
        __syncthreads();  // protect buf[cur] before next prefetch overwrites it
    }

    if (lane == 0) {
        g_part[b][seg][w][0] = mstate;
        g_part[b][seg][w][1] = lstate;
    }

    // combine row-halves, write partials
    float* buf = dyn;
    if (w >= 4) {
        int ds = w & 3;
#pragma unroll
        for (int h = 0; h < 8; h++) {
            float lo, hi;
            upk2(acc2[h], lo, hi);
            buf[(ds * 8 + h) * 64 + lane * 2] = lo;
            buf[(ds * 8 + h) * 64 + lane * 2 + 1] = hi;
        }
    }
    __syncthreads();
    if (w < 4) {
        int ds = w;
#pragma unroll
        for (int h = 0; h < 8; h++) {
            float lo, hi;
            upk2(acc2[h], lo, hi);
            lo += buf[(ds * 8 + h) * 64 + lane * 2];
            hi += buf[(ds * 8 + h) * 64 + lane * 2 + 1];
            g_part[b][seg][h][2 + ds * 64 + lane * 2] = lo;
            g_part[b][seg][h][2 + ds * 64 + lane * 2 + 1] = hi;
        }
    }

    // ---- last block for this b performs the merge -> ctxA ----
    __threadfence();
    __syncthreads();
    if (t == 0) {
        int old = atomicAdd(&g_syncnt[b], 1);
        s_last = (old == SEG - 1) ? 1 : 0;
        if (s_last) g_syncnt[b] = 0;
    }
    __syncthreads();
    if (s_last) {
        __threadfence();
#pragma unroll
        for (int h = 0; h < 8; h++) {
            float M = NEG_BIG;
#pragma unroll
            for (int s = 0; s < SEG; s++) M = fmaxf(M, g_part[b][s][h][0]);
            float L = 0.f, a = 0.f;
#pragma unroll
            for (int s = 0; s < SEG; s++) {
                float ms = g_part[b][s][h][0];
                float wg = (ms > 0.5f * NEG_BIG) ? expf(ms - M) : 0.f;
                L += wg * g_part[b][s][h][1];
                a += wg * g_part[b][s][h][2 + t];
            }
            g_ctxA[b][h * 256 + t] = a / L;
        }
        if (t == 0) g_ctxA[b][2048] = 1.f;
    }
}

// ======== GEMM2 (split-K): qpkpart = ctxA @ G ========
__global__ void __launch_bounds__(256) k_gemm2() {
    int n0 = blockIdx.x * 96, m0 = blockIdx.y * 32, s = blockIdx.z;
    int c0 = (s * 65) / 8, c1 = ((s + 1) * 65) / 8;
    int t = threadIdx.x, tx = t & 31, ty = t >> 5;
    __shared__ __align__(16) float As[32][33];
    __shared__ __align__(16) float Bs[32][96];
    float acc[4][3] = {};
    for (int c = c0; c < c1; c++) {
        int k0 = c * 32;
#pragma unroll
        for (int l = 0; l < 4; l++) {
            int idx = t + 256 * l;
            As[idx >> 5][idx & 31] = g_ctxA[m0 + (idx >> 5)][k0 + (idx & 31)];
        }
#pragma unroll
        for (int l = 0; l < 3; l++) {
            int idx = t + 256 * l;
            int r = idx / 24, cc = idx % 24;
            *(float4*)&Bs[r][cc * 4] = *(const float4*)&g_G[k0 + r][n0 + cc * 4];
        }
        __syncthreads();
#pragma unroll
        for (int kk = 0; kk < 32; kk++) {
            float a0 = As[ty * 4 + 0][kk], a1 = As[ty * 4 + 1][kk];
            float a2 = As[ty * 4 + 2][kk], a3 = As[ty * 4 + 3][kk];
            float b0 = Bs[kk][tx * 3 + 0], b1 = Bs[kk][tx * 3 + 1], b2 = Bs[kk][tx * 3 + 2];
            acc[0][0] += a0 * b0; acc[0][1] += a0 * b1; acc[0][2] += a0 * b2;
            acc[1][0] += a1 * b0; acc[1][1] += a1 * b1; acc[1][2] += a1 * b2;
            acc[2][0] += a2 * b0; acc[2][1] += a2 * b1; acc[2][2] += a2 * b2;
            acc[3][0] += a3 * b0; acc[3][1] += a3 * b1; acc[3][2] += a3 * b2;
        }
        __syncthreads();
    }
#pragma unroll
    for (int i = 0; i < 4; i++)
#pragma unroll
        for (int j = 0; j < 3; j++)
            g_qpkpart[s][m0 + ty * 4 + i][n0 + tx * 3 + j] = acc[i][j];
}

// ======== pointer logits + softmax + argmax + state for NEXT step ========
__global__ void __launch_bounds__(1024) k_pointsel(
    const float* __restrict__ x, const float* __restrict__ demand,
    float* __restrict__ out, int t_step, int write_route) {
    int b = blockIdx.x;
    int t = threadIdx.x, lane = t & 31, w = t >> 5;
    __shared__ float qs[Ec];
    __shared__ float u_s[Nc];
    __shared__ float s_ub;
    __shared__ float rv[32];
    __shared__ int ri[32];
    __shared__ float rs[32];
    __shared__ int redm[32];
    __shared__ int s_node;
    __shared__ float s_max, s_sum;

    float cap_old = g_cap[b];
    float cnt_old = g_cnt[b];

    if (t < 256) {
        float a = 0.f;
#pragma unroll
        for (int s = 0; s < 8; s++) a += g_qpkpart[s][b][t];
        qs[t] = a;
    } else if (t == 256) {
        float u = 0.f;
#pragma unroll
        for (int s = 0; s < 8; s++) u += g_qpkpart[s][b][256];
        s_ub = u;
    }
    __syncthreads();
    float ub = s_ub;
    ull q2[4];
    {
        float4 a0 = *(const float4*)&qs[lane * 8];
        float4 a1 = *(const float4*)&qs[lane * 8 + 4];
        q2[0] = pk2(a0.x, a0.y); q2[1] = pk2(a0.z, a0.w);
        q2[2] = pk2(a1.x, a1.y); q2[3] = pk2(a1.z, a1.w);
    }

    // phase A: 32 warps x 32 rows, 8-row batches
    int rbase = w * 32;
#pragma unroll
    for (int bch = 0; bch < 4; bch++) {
        float sr[8];
#pragma unroll
        for (int r = 0; r < 8; r++) {
            int n = rbase + bch * 8 + r;
            const float4* xr = (const float4*)(x + ((size_t)b * Nc + n) * Ec);
            float4 a0 = xr[lane * 2], a1 = xr[lane * 2 + 1];
            ull acc = 0ull;
            fma2(acc, pk2(a0.x, a0.y), q2[0]);
            fma2(acc, pk2(a0.z, a0.w), q2[1]);
            fma2(acc, pk2(a1.x, a1.y), q2[2]);
            fma2(acc, pk2(a1.z, a1.w), q2[3]);
            float lo, hi;
            upk2(acc, lo, hi);
            sr[r] = lo + hi;
        }
        float v = red8(sr, lane);
        if ((lane & 3) == 0) {
            int n = rbase + bch * 8 + (lane >> 2);
            u_s[n] = g_mask[b][n] ? NEG_BIG : CLIPC * tanhf(v + ub);
        }
    }
    __syncthreads();

    // phase B: argmax (first index), softmax, output
    float uv = u_s[t];
    float bv = uv;
    int bi = t;
#pragma unroll
    for (int off = 16; off; off >>= 1) {
        float ov = __shfl_xor_sync(0xffffffffu, bv, off);
        int oi = __shfl_xor_sync(0xffffffffu, bi, off);
        if (ov > bv || (ov == bv && oi < bi)) { bv = ov; bi = oi; }
    }
    if (lane == 0) { rv[w] = bv; ri[w] = bi; }
    __syncthreads();
    if (w == 0) {
        float v2 = rv[lane];
        int i2 = ri[lane];
#pragma unroll
        for (int off = 16; off; off >>= 1) {
            float ov = __shfl_xor_sync(0xffffffffu, v2, off);
            int oi = __shfl_xor_sync(0xffffffffu, i2, off);
            if (ov > v2 || (ov == v2 && oi < i2)) { v2 = ov; i2 = oi; }
        }
        if (lane == 0) { s_max = v2; s_node = i2; }
    }
    __syncthreads();
    float mx = s_max;
    int node = s_node;

    float p = expf(uv - mx);
    float ps = p;
#pragma unroll
    for (int off = 16; off; off >>= 1) ps += __shfl_xor_sync(0xffffffffu, ps, off);
    if (lane == 0) rs[w] = ps;
    __syncthreads();
    if (w == 0) {
        float s = rs[lane];
#pragma unroll
        for (int off = 16; off; off >>= 1) s += __shfl_xor_sync(0xffffffffu, s, off);
        if (lane == 0) s_sum = s;
    }
    __syncthreads();
    float inv = 1.f / s_sum;
    out[(size_t)t_step * Bc * Nc + (size_t)b * Nc + t] = p * inv;

    // ---- state update for next step ----
    float dnode = demand[(size_t)b * Nc + node];
    float cap_new = cap_old - dnode;
    int nz = (node != 0);
    float cnt_new = cnt_old - (nz ? 1.f : 0.f);

    int vo = g_visited[b][t];
    __syncthreads();
    if (t == 0) {
        if (write_route) out[(size_t)Tc * Bc * Nc + (size_t)t_step * Bc + b] = (float)node;
        g_cap[b] = cap_new;
        g_cur[b] = node;
        g_cnt[b] = cnt_new;
        if (nz) g_visited[b][node] = 1;
    }
    int vis = vo | ((t == node) ? nz : 0);
    int m = vis | (demand[(size_t)b * Nc + t] > cap_new);
    if (t == 0) m = (node == 0) ? 1 : m;
    g_mask[b][t] = (unsigned char)m;
    int am = __all_sync(0xffffffffu, m);
    if (lane == 0) redm[w] = am;

    float xn = x[((size_t)b * Nc + node) * Ec + (t & 255)];
    if (t < 256) {
        float sx = g_sumx[b][t] - (nz ? xn : 0.f);
        g_sumx[b][t] = sx;
        g_cat[b][t] = sx / cnt_new;
        g_cat[b][256 + t] = xn;
    } else if (t >= 514 && t < 544) {
        g_cat[b][t] = 0.f;
    }
    if (t == 0) { g_cat[b][512] = cap_new; g_cat[b][513] = 1.f; }
    __syncthreads();
    if (t == 0) {
        int a = 1;
#pragma unroll
        for (int k = 0; k < 32; k++) a &= redm[k];
        if (a) g_mask[b][0] = 0;
    }
}

// ---------------- launch ----------------
extern "C" void kernel_launch(void* const* d_in, const int* in_sizes, int n_in,
                              void* d_out, int out_size) {
    const float* x      = (const float*)d_in[0];
    const float* demand = (const float*)d_in[1];
    const float* cap0   = (const float*)d_in[2];
    const float* Wc     = (const float*)d_in[3];
    const float* bc     = (const float*)d_in[4];
    const float* Wqkv   = (const float*)d_in[5];
    const float* bqkv   = (const float*)d_in[6];
    const float* Wo     = (const float*)d_in[7];
    const float* bo     = (const float*)d_in[8];
    const float* Wpq    = (const float*)d_in[9];
    const float* bpq    = (const float*)d_in[10];
    const float* Wpk    = (const float*)d_in[11];
    const float* bpk    = (const float*)d_in[12];
    float* out = (float*)d_out;
    int write_route = (out_size > Tc * Bc * Nc) ? 1 : 0;

    const int attn_smem = (2 * XBUF_FLOATS + 32 * 12 + 8) * 4;
    cudaFuncSetAttribute(k_attn, cudaFuncAttributeMaxDynamicSharedMemorySize, attn_smem);

    kP1<<<1795, 256>>>(x, demand, cap0, Wc, bc, Wqkv, bqkv, Wo, bo, Wpq, bpq, Wpk);
    kP2<<<771, 288>>>(bqkv, bpk);

    for (int t = 0; t < Tc; t++) {
        k_gemm1<<<dim3(17, 8), 256>>>();
        k_attn<<<dim3(SEG, Bc), 256, attn_smem>>>(x);
        if (t == 0) pG<<<2049, 288>>>(Wqkv, bqkv);   // only needed before first gemm2
        k_gemm2<<<dim3(3, 8, 8), 256>>>();
        k_pointsel<<<Bc, 1024>>>(x, demand, out, t, write_route);
    }
}

// round 8
// speedup vs baseline: 2.3974x; 1.0549x over previous
#include <cuda_runtime.h>
#include <math.h>

#define Bc 256
#define Nc 1024
#define Ec 256
#define Hc 8
#define Tc 64
#define SEG 8
#define NSEG 128
#define SUBN 16
#define XPITCH 260
#define XBUF (SUBN * XPITCH)   // 4160 floats per buffer
#define NEG_BIG (-1e30f)
#define CLIPC 10.0f

#define K1 544
#define N1 2176
#define K2 2080
#define N2 288

typedef unsigned long long ull;

// ---------------- f32x2 packed helpers ----------------
__device__ __forceinline__ ull pk2(float lo, float hi) {
    ull r; asm("mov.b64 %0, {%1, %2};" : "=l"(r) : "f"(lo), "f"(hi)); return r;
}
__device__ __forceinline__ void upk2(ull v, float& lo, float& hi) {
    asm("mov.b64 {%0, %1}, %2;" : "=f"(lo), "=f"(hi) : "l"(v));
}
__device__ __forceinline__ void fma2(ull& d, ull a, ull b) {
    asm("fma.rn.f32x2 %0, %1, %2, %0;" : "+l"(d) : "l"(a), "l"(b));
}
__device__ __forceinline__ ull mul2(ull a, ull b) {
    ull r; asm("mul.rn.f32x2 %0, %1, %2;" : "=l"(r) : "l"(a), "l"(b)); return r;
}

// 8-value cross-lane sum reduction with redistribution: 16 shfl.
// On return, lane 4*k (k=0..7) holds the full sum of value k.
__device__ __forceinline__ float red8(float s[8], int lane) {
#pragma unroll
    for (int j = 0; j < 8; j++) s[j] += __shfl_xor_sync(0xffffffffu, s[j], 16);
    float k4[4];
    int hi16 = lane & 16;
#pragma unroll
    for (int j = 0; j < 4; j++) k4[j] = hi16 ? s[j + 4] : s[j];
#pragma unroll
    for (int j = 0; j < 4; j++) k4[j] += __shfl_xor_sync(0xffffffffu, k4[j], 8);
    float c0 = (lane & 8) ? k4[2] : k4[0];
    float c1 = (lane & 8) ? k4[3] : k4[1];
    c0 += __shfl_xor_sync(0xffffffffu, c0, 4);
    c1 += __shfl_xor_sync(0xffffffffu, c1, 4);
    float v = (lane & 4) ? c1 : c0;
    v += __shfl_xor_sync(0xffffffffu, v, 2);
    v += __shfl_xor_sync(0xffffffffu, v, 1);
    return v;
}

// ---------------- persistent device state ----------------
__device__ float g_sumx[Bc][Ec];
__device__ float g_cnt[Bc];
__device__ float g_cap[Bc];
__device__ int   g_cur[Bc];
__device__ unsigned char g_visited[Bc][Nc];
__device__ unsigned char g_mask[Bc][Nc];
__device__ float g_part[Bc][SEG][Hc][Ec + 2];
__device__ int   g_syncnt[Bc];
__device__ int   g_pscnt[Bc];
__device__ float g_u[Bc][Nc];

__device__ float g_A1[514][256];
__device__ float g_WkT[256][256];
__device__ float g_Wbig[K1][N1];
__device__ float g_cat[Bc][K1];
__device__ float g_qkflat[Bc][N1];
__device__ float g_T2ext[257][256];
__device__ float g_WpkT[256][256];
__device__ float g_T3ext[257][288];
__device__ float g_G[K2][N2];
__device__ float g_ctxA[Bc][K2];
__device__ float g_qpkpart[8][Bc][N2];

// ======== P1: everything that depends only on inputs ========
__global__ void kP1(const float* __restrict__ x, const float* __restrict__ demand,
                    const float* __restrict__ cap0,
                    const float* __restrict__ Wc, const float* __restrict__ bc,
                    const float* __restrict__ Wqkv, const float* __restrict__ bqkv,
                    const float* __restrict__ Wo, const float* __restrict__ bo,
                    const float* __restrict__ Wpq, const float* __restrict__ bpq,
                    const float* __restrict__ Wpk) {
    int blk = blockIdx.x, t = threadIdx.x;
    if (blk < 256) {
        int b = blk;
        __shared__ int red[8];
        const float* xb = x + (size_t)b * Nc * Ec;
        float s = 0.f;
        for (int n = 0; n < Nc; n++) s += xb[(size_t)n * Ec + t];
        g_sumx[b][t] = s;
        for (int i = t; i < Nc; i += 256) g_visited[b][i] = 0;
        float cap = cap0[b];
        if (t == 0) {
            g_cnt[b] = (float)Nc;
            g_cap[b] = cap;
            g_cur[b] = 0;
            g_syncnt[b] = 0;
            g_pscnt[b] = 0;
        }
        g_cat[b][t] = s / (float)Nc;
        g_cat[b][256 + t] = xb[t];
        if (t == 0) { g_cat[b][512] = cap; g_cat[b][513] = 1.f; }
        if (t < 30) g_cat[b][514 + t] = 0.f;
        int allm = 1;
        for (int n = t; n < Nc; n += 256) {
            int m = (demand[(size_t)b * Nc + n] > cap);
            if (n == 0) m = 1;
            g_mask[b][n] = (unsigned char)m;
            allm &= m;
        }
        allm = __all_sync(0xffffffffu, allm);
        if ((t & 31) == 0) red[t >> 5] = allm;
        __syncthreads();
        if (t == 0) {
            int a = 1;
            for (int w = 0; w < 8; w++) a &= red[w];
            if (a) g_mask[b][0] = 0;
        }
    } else if (blk < 512) {
        int d = blk - 256;
        g_WkT[d][t] = Wqkv[t * 768 + 256 + d];
    } else if (blk < 768) {
        int j2 = blk - 512;
        g_WpkT[j2][t] = Wpk[t * 256 + j2];
    } else if (blk < 1282) {
        int i = blk - 768;
        __shared__ float wrow[256];
        wrow[t] = (i < 513) ? Wc[i * 256 + t] : bc[t];
        __syncthreads();
        float s = (i == 513) ? bqkv[t] : 0.f;
        for (int e = 0; e < 256; e++) s += wrow[e] * Wqkv[e * 768 + t];
        g_A1[i][t] = s;
    } else if (blk < 1539) {
        int i = blk - 1282;
        __shared__ float wrow[256];
        wrow[t] = (i < 256) ? Wo[i * 256 + t] : bo[t];
        __syncthreads();
        float s = (i == 256) ? bpq[t] : 0.f;
        for (int k = 0; k < 256; k++) s += wrow[k] * Wpq[k * 256 + t];
        g_T2ext[i][t] = s;
    } else {
        int idx = (blk - 1539) * 256 + t;
        float* w = &g_Wbig[0][0];
        for (int i = idx; i < K1 * N1; i += 65536) w[i] = 0.f;
        float* g = &g_G[0][0];
        for (int i = idx; i < K2 * N2; i += 65536) g[i] = 0.f;
        for (int i = idx; i < Bc * 31; i += 65536) {
            int b = i / 31, j = i % 31;
            g_ctxA[b][2049 + j] = 0.f;
        }
    }
}

// ======== P2: Wbig (needs A1, WkT) + T3 (needs T2, WpkT) ========
__global__ void kP2(const float* __restrict__ bqkv, const float* __restrict__ bpk) {
    int blk = blockIdx.x, t = threadIdx.x;  // 288 threads
    if (blk < 514) {
        int i = blk;
        __shared__ float a1[256];
        if (t < 256) a1[t] = g_A1[i][t];
        __syncthreads();
        if (t < 256) {
            int e = t;
            const float scale = 0.17677669529663687f;
#pragma unroll
            for (int h = 0; h < 8; h++) {
                float s = 0.f;
#pragma unroll
                for (int dd = 0; dd < 32; dd++) s += a1[h * 32 + dd] * g_WkT[h * 32 + dd][e];
                g_Wbig[i][h * 256 + e] = scale * s;
            }
            if (e < 8) {
                float s = 0.f;
                for (int dd = 0; dd < 32; dd++) s += a1[e * 32 + dd] * bqkv[256 + e * 32 + dd];
                g_Wbig[i][2048 + e] = scale * s;
            }
        }
    } else {
        int j = blk - 514;
        __shared__ float t2[256];
        if (t < 256) t2[t] = g_T2ext[j][t];
        __syncthreads();
        if (t < 256) {
            float s = 0.f;
            for (int k = 0; k < 256; k++) s += t2[k] * g_WpkT[k][t];
            g_T3ext[j][t] = s;
        } else if (t == 256) {
            float s = 0.f;
            for (int k = 0; k < 256; k++) s += t2[k] * bpk[k];
            g_T3ext[j][256] = s;
        }
    }
}

// ======== pG: G fold (needs T3; only used by gemm2) ========
__global__ void pG(const float* __restrict__ Wqkv, const float* __restrict__ bqkv) {
    int he = blockIdx.x, t = threadIdx.x;
    __shared__ float sw[256];
    if (he < 2048) {
        int h = he >> 8, e = he & 255;
        if (t < 32) sw[t] = Wqkv[e * 768 + 512 + h * 32 + t];
        __syncthreads();
        if (t < 257) {
            float s = 0.f;
            int jb = h * 32;
#pragma unroll
            for (int jl = 0; jl < 32; jl++) s += sw[jl] * g_T3ext[jb + jl][t];
            g_G[he][t] = s;
        }
    } else {
        if (t < 256) sw[t] = bqkv[512 + t];
        __syncthreads();
        if (t < 257) {
            float s = g_T3ext[256][t];
            for (int j = 0; j < 256; j++) s += sw[j] * g_T3ext[j][t];
            g_G[2048][t] = s;
        }
    }
}

// ======== GEMM1: qkflat = cat @ Wbig ========
__global__ void __launch_bounds__(256) k_gemm1() {
    int n0 = blockIdx.x * 128, m0 = blockIdx.y * 32;
    int t = threadIdx.x, tx = t & 31, ty = t >> 5;
    __shared__ __align__(16) float As[32][33];
    __shared__ __align__(16) float Bs[32][128];
    ull acc2[4][2];
#pragma unroll
    for (int i = 0; i < 4; i++) { acc2[i][0] = 0ull; acc2[i][1] = 0ull; }
    for (int k0 = 0; k0 < K1; k0 += 32) {
#pragma unroll
        for (int l = 0; l < 4; l++) {
            int idx = t + 256 * l;
            As[idx >> 5][idx & 31] = g_cat[m0 + (idx >> 5)][k0 + (idx & 31)];
        }
#pragma unroll
        for (int l = 0; l < 4; l++) {
            int idx = t + 256 * l;
            int r = idx >> 5, c = idx & 31;
            *(float4*)&Bs[r][c * 4] = *(const float4*)&g_Wbig[k0 + r][n0 + c * 4];
        }
        __syncthreads();
#pragma unroll
        for (int kk = 0; kk < 32; kk++) {
            ulonglong2 bv = *(const ulonglong2*)&Bs[kk][tx * 4];
#pragma unroll
            for (int i = 0; i < 4; i++) {
                float a = As[ty * 4 + i][kk];
                ull ad = pk2(a, a);
                fma2(acc2[i][0], ad, bv.x);
                fma2(acc2[i][1], ad, bv.y);
            }
        }
        __syncthreads();
    }
#pragma unroll
    for (int i = 0; i < 4; i++) {
        float4 v;
        upk2(acc2[i][0], v.x, v.y);
        upk2(acc2[i][1], v.z, v.w);
        *(float4*)&g_qkflat[m0 + ty * 4 + i][n0 + tx * 4] = v;
    }
}

// ======== K2: flash attention, two independent 4-warp pipelines ========
// Group g (warps 4g..4g+3) processes chunks {g, g+2, g+4, g+6} of 16 rows,
// with its own cp.async double-buffer and named barrier (1+g). Groups merge
// flash state at the end, then the cross-SEG atomic merge as before.
__global__ void __launch_bounds__(256, 2)
k_attn(const float* __restrict__ x) {
    extern __shared__ __align__(16) float dyn[];
    int seg = blockIdx.x, b = blockIdx.y;
    int t = threadIdx.x, lane = t & 31, w = t >> 5;
    int g = w >> 2, wg = w & 3, tg = t & 127;

    float* xgrp = dyn + g * 2 * XBUF;                 // this group's 2 buffers
    float* ssg  = dyn + 4 * XBUF + g * 192;           // [16][12]
    float* alg  = dyn + 4 * XBUF + 384 + g * 8;       // [8] alphas
    __shared__ int s_last;

    ull qkr2[8][4];
#pragma unroll
    for (int h = 0; h < 8; h++) {
        float4 q0 = *(const float4*)&g_qkflat[b][h * 256 + lane * 8];
        float4 q1 = *(const float4*)&g_qkflat[b][h * 256 + lane * 8 + 4];
        qkr2[h][0] = pk2(q0.x, q0.y); qkr2[h][1] = pk2(q0.z, q0.w);
        qkr2[h][2] = pk2(q1.x, q1.y); qkr2[h][3] = pk2(q1.z, q1.w);
    }
    int hsm = 2 * wg + (lane >> 4);                   // softmax head (half-warp)
    float sbh = g_qkflat[b][2048 + hsm];

    ull acc2[8];
#pragma unroll
    for (int h = 0; h < 8; h++) acc2[h] = 0ull;
    float mstate = NEG_BIG, lstate = 0.f;

    int n0 = seg * NSEG + g * SUBN;                   // group chunk base
    unsigned sbase = (unsigned)__cvta_generic_to_shared(xgrp);
    int srow = tg >> 3, scb = tg & 7;

    // prologue: stage chunk 0 into buffer 0
    {
        const float4* src = (const float4*)(x + ((size_t)b * Nc + n0) * Ec);
#pragma unroll
        for (int i = 0; i < 8; i++) {
            int c4 = scb + i * 8;
            unsigned d = sbase + (unsigned)(srow * (XPITCH * 4) + c4 * 16);
            asm volatile("cp.async.cg.shared.global [%0], [%1], 16;"
                         :: "r"(d), "l"(src + srow * 64 + c4));
        }
        asm volatile("cp.async.commit_group;");
    }

#pragma unroll
    for (int c = 0; c < 4; c++) {
        int ni = n0 + c * 32;
        asm volatile("cp.async.wait_group 0;" ::: "memory");
        asm volatile("bar.sync %0, 128;" :: "r"(1 + g) : "memory");
        if (c < 3) {   // prefetch next chunk (buffer safe: all group threads passed acc(c-1))
            const float4* src = (const float4*)(x + ((size_t)b * Nc + ni + 32) * Ec);
            unsigned bufo = sbase + (unsigned)(((c + 1) & 1) * XBUF * 4);
#pragma unroll
            for (int i = 0; i < 8; i++) {
                int c4 = scb + i * 8;
                unsigned d = bufo + (unsigned)(srow * (XPITCH * 4) + c4 * 16);
                asm volatile("cp.async.cg.shared.global [%0], [%1], 16;"
                             :: "r"(d), "l"(src + srow * 64 + c4));
            }
            asm volatile("cp.async.commit_group;");
        }
        const float* xs = xgrp + (c & 1) * XBUF;

        // ---- scores: warp wg rows wg*4..wg*4+3, all heads ----
#pragma unroll
        for (int i = 0; i < 4; i++) {
            int nl = wg * 4 + i;
            float4 xv0 = *(const float4*)&xs[nl * XPITCH + lane * 8];
            float4 xv1 = *(const float4*)&xs[nl * XPITCH + lane * 8 + 4];
            ull x2[4] = {pk2(xv0.x, xv0.y), pk2(xv0.z, xv0.w),
                         pk2(xv1.x, xv1.y), pk2(xv1.z, xv1.w)};
            float s[8];
#pragma unroll
            for (int h = 0; h < 8; h++) {
                ull s2 = 0ull;
#pragma unroll
                for (int j = 0; j < 4; j++) fma2(s2, qkr2[h][j], x2[j]);
                float lo, hi;
                upk2(s2, lo, hi);
                s[h] = lo + hi;
            }
            float v = red8(s, lane);
            if ((lane & 3) == 0) {
                int h = lane >> 2;
                ssg[nl * 12 + h] = g_mask[b][ni + nl] ? NEG_BIG : v;
            }
        }
        asm volatile("bar.sync %0, 128;" :: "r"(1 + g) : "memory");

        // ---- online softmax: half-warp per head ----
        {
            float raw = ssg[(lane & 15) * 12 + hsm];
            float v = (raw < -1e29f) ? NEG_BIG : raw + sbh;
            float mx = v;
#pragma unroll
            for (int off = 8; off; off >>= 1)
                mx = fmaxf(mx, __shfl_xor_sync(0xffffffffu, mx, off));
            float mnew = fmaxf(mstate, mx);
            float alpha = (mstate > 0.5f * NEG_BIG) ? expf(mstate - mnew) : 0.f;
            float p = (v > 0.5f * NEG_BIG) ? expf(v - mnew) : 0.f;
            ssg[(lane & 15) * 12 + hsm] = p;
            float ps = p;
#pragma unroll
            for (int off = 8; off; off >>= 1)
                ps += __shfl_xor_sync(0xffffffffu, ps, off);
            lstate = lstate * alpha + ps;
            mstate = mnew;
            if ((lane & 15) == 0) alg[hsm] = alpha;
        }
        asm volatile("bar.sync %0, 128;" :: "r"(1 + g) : "memory");

        // ---- acc: warp wg owns dims wg*64.., all heads, x read once ----
        {
#pragma unroll
            for (int h = 0; h < 8; h++) {
                float a = alg[h];
                acc2[h] = mul2(acc2[h], pk2(a, a));
            }
#pragma unroll
            for (int r = 0; r < 16; r++) {
                float2 xv = *(const float2*)&xs[r * XPITCH + wg * 64 + lane * 2];
                ull xp = pk2(xv.x, xv.y);
                float4 pa = *(const float4*)&ssg[r * 12];
                float4 pb = *(const float4*)&ssg[r * 12 + 4];
                fma2(acc2[0], pk2(pa.x, pa.x), xp);
                fma2(acc2[1], pk2(pa.y, pa.y), xp);
                fma2(acc2[2], pk2(pa.z, pa.z), xp);
                fma2(acc2[3], pk2(pa.w, pa.w), xp);
                fma2(acc2[4], pk2(pb.x, pb.x), xp);
                fma2(acc2[5], pk2(pb.y, pb.y), xp);
                fma2(acc2[6], pk2(pb.z, pb.z), xp);
                fma2(acc2[7], pk2(pb.w, pb.w), xp);
            }
        }
    }

    // ---- cross-group merge (reuse xbuf region) ----
    __syncthreads();
    float* macc = dyn;            // [8][256]
    float* mml  = dyn + 2048;     // [8][2]
    float* mf   = dyn + 2064;     // [8][2]
    if (g == 1) {
        if ((lane & 15) == 0) { mml[hsm * 2] = mstate; mml[hsm * 2 + 1] = lstate; }
#pragma unroll
        for (int h = 0; h < 8; h++) {
            float lo, hi;
            upk2(acc2[h], lo, hi);
            *(float2*)&macc[h * 256 + wg * 64 + lane * 2] = make_float2(lo, hi);
        }
    }
    __syncthreads();
    if (g == 0 && (lane & 15) == 0) {
        float mB = mml[hsm * 2], lB = mml[hsm * 2 + 1];
        float M = fmaxf(mstate, mB);
        float fA = (mstate > 0.5f * NEG_BIG) ? expf(mstate - M) : 0.f;
        float fB = (mB > 0.5f * NEG_BIG) ? expf(mB - M) : 0.f;
        g_part[b][seg][hsm][0] = M;
        g_part[b][seg][hsm][1] = fA * lstate + fB * lB;
        mf[hsm * 2] = fA; mf[hsm * 2 + 1] = fB;
    }
    __syncthreads();
    if (g == 0) {
#pragma unroll
        for (int h = 0; h < 8; h++) {
            float lo, hi;
            upk2(acc2[h], lo, hi);
            float fA = mf[h * 2], fB = mf[h * 2 + 1];
            int d0 = wg * 64 + lane * 2;
            float2 bm = *(const float2*)&macc[h * 256 + d0];
            *(float2*)&g_part[b][seg][h][2 + d0] =
                make_float2(fA * lo + fB * bm.x, fA * hi + fB * bm.y);
        }
    }

    // ---- last SEG block for this b performs the merge -> ctxA ----
    __threadfence();
    __syncthreads();
    if (t == 0) {
        int old = atomicAdd(&g_syncnt[b], 1);
        s_last = (old == SEG - 1) ? 1 : 0;
        if (s_last) g_syncnt[b] = 0;
    }
    __syncthreads();
    if (s_last) {
        __threadfence();
#pragma unroll
        for (int h = 0; h < 8; h++) {
            float M = NEG_BIG;
#pragma unroll
            for (int s = 0; s < SEG; s++) M = fmaxf(M, g_part[b][s][h][0]);
            float L = 0.f, a = 0.f;
#pragma unroll
            for (int s = 0; s < SEG; s++) {
                float ms = g_part[b][s][h][0];
                float wgt = (ms > 0.5f * NEG_BIG) ? expf(ms - M) : 0.f;
                L += wgt * g_part[b][s][h][1];
                a += wgt * g_part[b][s][h][2 + t];
            }
            g_ctxA[b][h * 256 + t] = a / L;
        }
        if (t == 0) g_ctxA[b][2048] = 1.f;
    }
}

// ======== GEMM2 (split-K): qpkpart = ctxA @ G ========
__global__ void __launch_bounds__(256) k_gemm2() {
    int n0 = blockIdx.x * 96, m0 = blockIdx.y * 32, s = blockIdx.z;
    int c0 = (s * 65) / 8, c1 = ((s + 1) * 65) / 8;
    int t = threadIdx.x, tx = t & 31, ty = t >> 5;
    __shared__ __align__(16) float As[32][33];
    __shared__ __align__(16) float Bs[32][96];
    float acc[4][3] = {};
    for (int c = c0; c < c1; c++) {
        int k0 = c * 32;
#pragma unroll
        for (int l = 0; l < 4; l++) {
            int idx = t + 256 * l;
            As[idx >> 5][idx & 31] = g_ctxA[m0 + (idx >> 5)][k0 + (idx & 31)];
        }
#pragma unroll
        for (int l = 0; l < 3; l++) {
            int idx = t + 256 * l;
            int r = idx / 24, cc = idx % 24;
            *(float4*)&Bs[r][cc * 4] = *(const float4*)&g_G[k0 + r][n0 + cc * 4];
        }
        __syncthreads();
#pragma unroll
        for (int kk = 0; kk < 32; kk++) {
            float a0 = As[ty * 4 + 0][kk], a1 = As[ty * 4 + 1][kk];
            float a2 = As[ty * 4 + 2][kk], a3 = As[ty * 4 + 3][kk];
            float b0 = Bs[kk][tx * 3 + 0], b1 = Bs[kk][tx * 3 + 1], b2 = Bs[kk][tx * 3 + 2];
            acc[0][0] += a0 * b0; acc[0][1] += a0 * b1; acc[0][2] += a0 * b2;
            acc[1][0] += a1 * b0; acc[1][1] += a1 * b1; acc[1][2] += a1 * b2;
            acc[2][0] += a2 * b0; acc[2][1] += a2 * b1; acc[2][2] += a2 * b2;
            acc[3][0] += a3 * b0; acc[3][1] += a3 * b1; acc[3][2] += a3 * b2;
        }
        __syncthreads();
    }
#pragma unroll
    for (int i = 0; i < 4; i++)
#pragma unroll
        for (int j = 0; j < 3; j++)
            g_qpkpart[s][m0 + ty * 4 + i][n0 + tx * 3 + j] = acc[i][j];
}

// ======== pointer logits (4 blocks/b) + last-block select/update ========
__global__ void __launch_bounds__(256) k_pointsel(
    const float* __restrict__ x, const float* __restrict__ demand,
    float* __restrict__ out, int t_step, int write_route) {
    int s = blockIdx.x, b = blockIdx.y;
    int t = threadIdx.x, lane = t & 31, w = t >> 5;
    __shared__ float qs[Ec];
    __shared__ float s_ub;
    __shared__ int slast;
    __shared__ float rv[8];
    __shared__ int ri[8];
    __shared__ float rs[8];
    __shared__ int redm[8];
    __shared__ int s_node;
    __shared__ float s_max, s_sum;

    {   // split-K reduce of qpk (redundant per block, L2-hot)
        float a = 0.f;
#pragma unroll
        for (int k = 0; k < 8; k++) a += g_qpkpart[k][b][t];
        qs[t] = a;
        if (t == 0) {
            float u = 0.f;
#pragma unroll
            for (int k = 0; k < 8; k++) u += g_qpkpart[k][b][256];
            s_ub = u;
        }
    }
    __syncthreads();
    float ub = s_ub;
    ull q2[4];
    {
        float4 a0 = *(const float4*)&qs[lane * 8];
        float4 a1 = *(const float4*)&qs[lane * 8 + 4];
        q2[0] = pk2(a0.x, a0.y); q2[1] = pk2(a0.z, a0.w);
        q2[2] = pk2(a1.x, a1.y); q2[3] = pk2(a1.z, a1.w);
    }

    // phase A: this block covers rows s*256 .. s*256+255 (8 warps x 32 rows)
    int rbase = s * 256 + w * 32;
#pragma unroll
    for (int bch = 0; bch < 4; bch++) {
        float sr[8];
#pragma unroll
        for (int r = 0; r < 8; r++) {
            int n = rbase + bch * 8 + r;
            const float4* xr = (const float4*)(x + ((size_t)b * Nc + n) * Ec);
            float4 a0 = xr[lane * 2], a1 = xr[lane * 2 + 1];
            ull acc = 0ull;
            fma2(acc, pk2(a0.x, a0.y), q2[0]);
            fma2(acc, pk2(a0.z, a0.w), q2[1]);
            fma2(acc, pk2(a1.x, a1.y), q2[2]);
            fma2(acc, pk2(a1.z, a1.w), q2[3]);
            float lo, hi;
            upk2(acc, lo, hi);
            sr[r] = lo + hi;
        }
        float v = red8(sr, lane);
        if ((lane & 3) == 0) {
            int n = rbase + bch * 8 + (lane >> 2);
            g_u[b][n] = g_mask[b][n] ? NEG_BIG : CLIPC * tanhf(v + ub);
        }
    }

    // last block per b does selection + output + state update
    __threadfence();
    __syncthreads();
    if (t == 0) {
        int old = atomicAdd(&g_pscnt[b], 1);
        slast = (old == 3) ? 1 : 0;
        if (slast) g_pscnt[b] = 0;
    }
    __syncthreads();
    if (!slast) return;
    __threadfence();

    float cap_old = g_cap[b];
    float cnt_old = g_cnt[b];

    // argmax (first-index tie) over 1024 logits, 4 per thread
    float uv[4];
    float bv = -3.4e38f; int bi = 0x7fffffff;
#pragma unroll
    for (int k = 0; k < 4; k++) {
        int n = t + 256 * k;
        uv[k] = g_u[b][n];
        if (uv[k] > bv) { bv = uv[k]; bi = n; }
    }
#pragma unroll
    for (int off = 16; off; off >>= 1) {
        float ov = __shfl_xor_sync(0xffffffffu, bv, off);
        int oi = __shfl_xor_sync(0xffffffffu, bi, off);
        if (ov > bv || (ov == bv && oi < bi)) { bv = ov; bi = oi; }
    }
    if (lane == 0) { rv[w] = bv; ri[w] = bi; }
    __syncthreads();
    if (t == 0) {
        float mv = rv[0]; int mi = ri[0];
#pragma unroll
        for (int k = 1; k < 8; k++)
            if (rv[k] > mv || (rv[k] == mv && ri[k] < mi)) { mv = rv[k]; mi = ri[k]; }
        s_max = mv; s_node = mi;
    }
    __syncthreads();
    float mx = s_max;
    int node = s_node;

    float pk[4];
    float psum = 0.f;
#pragma unroll
    for (int k = 0; k < 4; k++) { pk[k] = expf(uv[k] - mx); psum += pk[k]; }
#pragma unroll
    for (int off = 16; off; off >>= 1) psum += __shfl_xor_sync(0xffffffffu, psum, off);
    if (lane == 0) rs[w] = psum;
    __syncthreads();
    if (t == 0) {
        float ss = 0.f;
#pragma unroll
        for (int k = 0; k < 8; k++) ss += rs[k];
        s_sum = ss;
    }
    __syncthreads();
    float inv = 1.f / s_sum;
    size_t ob = (size_t)t_step * Bc * Nc + (size_t)b * Nc;
#pragma unroll
    for (int k = 0; k < 4; k++) out[ob + t + 256 * k] = pk[k] * inv;

    // ---- state update for next step ----
    float dnode = demand[(size_t)b * Nc + node];
    float cap_new = cap_old - dnode;
    int nz = (node != 0);
    float cnt_new = cnt_old - (nz ? 1.f : 0.f);

    int vo[4];
#pragma unroll
    for (int k = 0; k < 4; k++) vo[k] = g_visited[b][t + 256 * k];
    __syncthreads();
    if (t == 0) {
        if (write_route) out[(size_t)Tc * Bc * Nc + (size_t)t_step * Bc + b] = (float)node;
        g_cap[b] = cap_new;
        g_cur[b] = node;
        g_cnt[b] = cnt_new;
        if (nz) g_visited[b][node] = 1;
    }
    int allm = 1;
#pragma unroll
    for (int k = 0; k < 4; k++) {
        int n = t + 256 * k;
        int vis = vo[k] | ((n == node) ? nz : 0);
        int m = vis | (demand[(size_t)b * Nc + n] > cap_new);
        if (n == 0) m = (node == 0) ? 1 : m;
        g_mask[b][n] = (unsigned char)m;
        allm &= m;
    }
    allm = __all_sync(0xffffffffu, allm);
    if (lane == 0) redm[w] = allm;

    float xn = x[((size_t)b * Nc + node) * Ec + t];
    float sx = g_sumx[b][t] - (nz ? xn : 0.f);
    g_sumx[b][t] = sx;
    g_cat[b][t] = sx / cnt_new;
    g_cat[b][256 + t] = xn;
    if (t == 0) { g_cat[b][512] = cap_new; g_cat[b][513] = 1.f; }
    __syncthreads();
    if (t == 0) {
        int a = 1;
#pragma unroll
        for (int k = 0; k < 8; k++) a &= redm[k];
        if (a) g_mask[b][0] = 0;
    }
}

// ---------------- launch ----------------
extern "C" void kernel_launch(void* const* d_in, const int* in_sizes, int n_in,
                              void* d_out, int out_size) {
    const float* x      = (const float*)d_in[0];
    const float* demand = (const float*)d_in[1];
    const float* cap0   = (const float*)d_in[2];
    const float* Wc     = (const float*)d_in[3];
    const float* bc     = (const float*)d_in[4];
    const float* Wqkv   = (const float*)d_in[5];
    const float* bqkv   = (const float*)d_in[6];
    const float* Wo     = (const float*)d_in[7];
    const float* bo     = (const float*)d_in[8];
    const float* Wpq    = (const float*)d_in[9];
    const float* bpq    = (const float*)d_in[10];
    const float* Wpk    = (const float*)d_in[11];
    const float* bpk    = (const float*)d_in[12];
    float* out = (float*)d_out;
    int write_route = (out_size > Tc * Bc * Nc) ? 1 : 0;

    const int attn_smem = (4 * XBUF + 2 * 192 + 16) * 4;
    cudaFuncSetAttribute(k_attn, cudaFuncAttributeMaxDynamicSharedMemorySize, attn_smem);

    kP1<<<1795, 256>>>(x, demand, cap0, Wc, bc, Wqkv, bqkv, Wo, bo, Wpq, bpq, Wpk);
    kP2<<<771, 288>>>(bqkv, bpk);

    for (int t = 0; t < Tc; t++) {
        k_gemm1<<<dim3(17, 8), 256>>>();
        k_attn<<<dim3(SEG, Bc), 256, attn_smem>>>(x);
        if (t == 0) pG<<<2049, 288>>>(Wqkv, bqkv);   // only needed before first gemm2
        k_gemm2<<<dim3(3, 8, 8), 256>>>();
        k_pointsel<<<dim3(4, Bc), 256>>>(x, demand, out, t, write_route);
    }
}